// round 2
// baseline (speedup 1.0000x reference)
#include <cuda_runtime.h>
#include <math.h>

#define NN 16384
#define GIN 1568

// ---------------- scratch (static __device__, no allocation) ----------------
__device__ float d_c1buf[(size_t)NN * 16 * 14 * 14];   // conv1 pooled out  [N,16,14,14]
__device__ float d_h0[(size_t)NN * GIN];               // conv2 pooled flat [N,1568]
__device__ float d_xl1[(size_t)NN * 128];
__device__ float d_xr1[(size_t)NN * 128];
__device__ float d_h1[(size_t)NN * 128];
__device__ float d_xl2[(size_t)NN * 64];
__device__ float d_xr2[(size_t)NN * 64];
__device__ float d_h2[(size_t)NN * 64];
__device__ float d_alpha1[(size_t)(524288 + NN) * 2];
__device__ float d_alpha2[(size_t)(524288 + NN)];
__device__ unsigned d_amax1[NN * 2];
__device__ float d_denom1[NN * 2];
__device__ unsigned d_amax2[NN];
__device__ float d_denom2[NN];

// ---------------- helpers ----------------
__device__ __forceinline__ unsigned fenc(float f) {
    unsigned b = __float_as_uint(f);
    return b ^ ((b >> 31) ? 0xFFFFFFFFu : 0x80000000u);
}
__device__ __forceinline__ float fdec(unsigned u) {
    return __uint_as_float(u ^ ((u >> 31) ? 0x80000000u : 0xFFFFFFFFu));
}
#define ENC_NEG_INF 0x007FFFFFu   // fenc(-inf)

// ---------------- conv1 + relu + maxpool2 ----------------
// x [N,1,28,28] -> d_c1buf [N,16,14,14]
__global__ void k_conv1(const float* __restrict__ x,
                        const float* __restrict__ w,
                        const float* __restrict__ b) {
    __shared__ float sIn[784];
    __shared__ float sW[144];
    __shared__ float sB[16];
    int n = blockIdx.x, tid = threadIdx.x;
    const float* xp = x + (size_t)n * 784;
    for (int i = tid; i < 784; i += 256) sIn[i] = xp[i];
    if (tid < 144) sW[tid] = w[tid];
    if (tid < 16) sB[tid] = b[tid];
    __syncthreads();
    for (int o = tid; o < 16 * 196; o += 256) {
        int c = o / 196, r = o % 196, py = r / 14, px = r % 14;
        float best = -1e30f;
        #pragma unroll
        for (int dy = 0; dy < 2; dy++) {
            #pragma unroll
            for (int dx = 0; dx < 2; dx++) {
                int y = 2 * py + dy, xx = 2 * px + dx;
                float v = sB[c];
                #pragma unroll
                for (int ky = 0; ky < 3; ky++) {
                    int iy = y + ky - 1;
                    if ((unsigned)iy < 28u) {
                        #pragma unroll
                        for (int kx = 0; kx < 3; kx++) {
                            int ix = xx + kx - 1;
                            if ((unsigned)ix < 28u)
                                v += sIn[iy * 28 + ix] * sW[c * 9 + ky * 3 + kx];
                        }
                    }
                }
                best = fmaxf(best, v);
            }
        }
        d_c1buf[(size_t)n * 3136 + o] = fmaxf(best, 0.f);
    }
}

// ---------------- conv2 + relu + maxpool2 ----------------
// d_c1buf [N,16,14,14] -> d_h0 [N, 32*7*7 = 1568]
__global__ void k_conv2(const float* __restrict__ w,
                        const float* __restrict__ b) {
    __shared__ float sIn[3136];
    __shared__ float sW[4608];
    __shared__ float sB[32];
    int n = blockIdx.x, tid = threadIdx.x;
    const float* ip = d_c1buf + (size_t)n * 3136;
    for (int i = tid; i < 3136; i += 256) sIn[i] = ip[i];
    for (int i = tid; i < 4608; i += 256) sW[i] = __ldg(&w[i]);
    if (tid < 32) sB[tid] = b[tid];
    __syncthreads();
    for (int o = tid; o < 1568; o += 256) {
        int c = o / 49, r = o % 49, py = r / 7, px = r % 7;
        float best = -1e30f;
        #pragma unroll
        for (int dy = 0; dy < 2; dy++) {
            #pragma unroll
            for (int dx = 0; dx < 2; dx++) {
                int y = 2 * py + dy, xx = 2 * px + dx;
                float v = sB[c];
                for (int ci = 0; ci < 16; ci++) {
                    const float* inp = &sIn[ci * 196];
                    const float* wp = &sW[(c * 16 + ci) * 9];
                    #pragma unroll
                    for (int ky = 0; ky < 3; ky++) {
                        int iy = y + ky - 1;
                        if ((unsigned)iy < 14u) {
                            #pragma unroll
                            for (int kx = 0; kx < 3; kx++) {
                                int ix = xx + kx - 1;
                                if ((unsigned)ix < 14u)
                                    v += inp[iy * 14 + ix] * wp[ky * 3 + kx];
                            }
                        }
                    }
                }
                best = fmaxf(best, v);
            }
        }
        d_h0[(size_t)n * 1568 + o] = fmaxf(best, 0.f);
    }
}

// ---------------- SGEMM: C = A(MxK) * B(KxNc) + bias ----------------
// SEL picks scratch A/C (no cudaGetSymbolAddress needed):
// 0: A=d_h0, C=d_xl1 ; 1: A=d_h0, C=d_xr1 ; 2: A=relu(d_h1), C=d_xl2 ; 3: A=relu(d_h1), C=d_xr2
template <int SEL>
__global__ void k_gemm(const float* __restrict__ B,
                       const float* __restrict__ bias,
                       int K, int Nc) {
    const float* A = (SEL < 2) ? d_h0 : d_h1;
    float* C;
    if (SEL == 0) C = d_xl1;
    else if (SEL == 1) C = d_xr1;
    else if (SEL == 2) C = d_xl2;
    else C = d_xr2;

    __shared__ float As[16][64];
    __shared__ float Bs[16][64];
    int bm = blockIdx.y * 64, bn = blockIdx.x * 64;
    int tid = threadIdx.x;
    int ar = tid >> 2, ac = (tid & 3) << 2;
    int br = tid >> 4, bc4 = (tid & 15) << 2;
    int ty = tid >> 4, tx = tid & 15;
    float acc[4][4] = {};

    for (int k0 = 0; k0 < K; k0 += 16) {
        float4 av = *(const float4*)&A[(size_t)(bm + ar) * K + k0 + ac];
        if (SEL >= 2) {  // fused ReLU on layer-1 output
            av.x = fmaxf(av.x, 0.f); av.y = fmaxf(av.y, 0.f);
            av.z = fmaxf(av.z, 0.f); av.w = fmaxf(av.w, 0.f);
        }
        As[ac + 0][ar] = av.x;
        As[ac + 1][ar] = av.y;
        As[ac + 2][ar] = av.z;
        As[ac + 3][ar] = av.w;
        float4 bv = *(const float4*)&B[(size_t)(k0 + br) * Nc + bn + bc4];
        *(float4*)&Bs[br][bc4] = bv;
        __syncthreads();
        #pragma unroll
        for (int k = 0; k < 16; k++) {
            float a[4], bb[4];
            #pragma unroll
            for (int i = 0; i < 4; i++) a[i] = As[k][ty * 4 + i];
            #pragma unroll
            for (int j = 0; j < 4; j++) bb[j] = Bs[k][tx * 4 + j];
            #pragma unroll
            for (int i = 0; i < 4; i++)
                #pragma unroll
                for (int j = 0; j < 4; j++) acc[i][j] += a[i] * bb[j];
        }
        __syncthreads();
    }
    #pragma unroll
    for (int i = 0; i < 4; i++) {
        #pragma unroll
        for (int j = 0; j < 4; j++) {
            int row = bm + ty * 4 + i, col = bn + tx * 4 + j;
            C[(size_t)row * Nc + col] = acc[i][j] + bias[col];
        }
    }
}

// ---------------- init kernels ----------------
__global__ void k_init1(const float* __restrict__ bias1) {
    int i = blockIdx.x * blockDim.x + threadIdx.x;
    if (i < NN * 128) d_h1[i] = bias1[i & 127];
    if (i < NN * 2) { d_amax1[i] = ENC_NEG_INF; d_denom1[i] = 0.f; }
}
__global__ void k_init2(const float* __restrict__ bias2) {
    int i = blockIdx.x * blockDim.x + threadIdx.x;
    if (i < NN * 64) d_h2[i] = bias2[i & 63];
    if (i < NN) { d_amax2[i] = ENC_NEG_INF; d_denom2[i] = 0.f; }
}

// ---------------- GAT layer 1 edge kernels (H=2, C=64) ----------------
__global__ void k_alpha1(const int* __restrict__ ei, const float* __restrict__ att,
                         int Eraw, int Etot) {
    int w = (blockIdx.x * blockDim.x + threadIdx.x) >> 5;
    if (w >= Etot) return;
    int lane = threadIdx.x & 31;
    int s, d;
    if (w < Eraw) { s = __ldg(&ei[w]); d = __ldg(&ei[Eraw + w]); } else { s = d = w - Eraw; }
    const float* xl = d_xl1 + (size_t)s * 128;
    const float* xr = d_xr1 + (size_t)d * 128;
    float p0 = 0.f, p1 = 0.f;
    #pragma unroll
    for (int i = 0; i < 2; i++) {
        int c = lane + i * 32;
        float v = xl[c] + xr[c];
        v = v > 0.f ? v : 0.2f * v;
        p0 += v * att[c];
        int c2 = c + 64;
        float v2 = xl[c2] + xr[c2];
        v2 = v2 > 0.f ? v2 : 0.2f * v2;
        p1 += v2 * att[c2];
    }
    #pragma unroll
    for (int o = 16; o > 0; o >>= 1) {
        p0 += __shfl_down_sync(0xFFFFFFFFu, p0, o);
        p1 += __shfl_down_sync(0xFFFFFFFFu, p1, o);
    }
    if (lane == 0) {
        d_alpha1[(size_t)w * 2] = p0;
        d_alpha1[(size_t)w * 2 + 1] = p1;
        atomicMax(&d_amax1[d * 2], fenc(p0));
        atomicMax(&d_amax1[d * 2 + 1], fenc(p1));
    }
}

__global__ void k_exp1(const int* __restrict__ ei, int Eraw, int Etot) {
    int i = blockIdx.x * blockDim.x + threadIdx.x;
    if (i >= Etot * 2) return;
    int e = i >> 1, h = i & 1;
    int d = (e < Eraw) ? __ldg(&ei[Eraw + e]) : e - Eraw;
    float ex = __expf(d_alpha1[i] - fdec(d_amax1[d * 2 + h]));
    d_alpha1[i] = ex;
    atomicAdd(&d_denom1[d * 2 + h], ex);
}

__global__ void k_scat1(const int* __restrict__ ei, int Eraw, int Etot) {
    int w = (blockIdx.x * blockDim.x + threadIdx.x) >> 5;
    if (w >= Etot) return;
    int lane = threadIdx.x & 31;
    int s, d;
    if (w < Eraw) { s = __ldg(&ei[w]); d = __ldg(&ei[Eraw + w]); } else { s = d = w - Eraw; }
    float a0 = d_alpha1[(size_t)w * 2] / d_denom1[d * 2];
    float a1 = d_alpha1[(size_t)w * 2 + 1] / d_denom1[d * 2 + 1];
    const float* xl = d_xl1 + (size_t)s * 128;
    float* op = d_h1 + (size_t)d * 128;
    atomicAdd(&op[lane],      xl[lane]      * a0);
    atomicAdd(&op[lane + 32], xl[lane + 32] * a0);
    atomicAdd(&op[lane + 64], xl[lane + 64] * a1);
    atomicAdd(&op[lane + 96], xl[lane + 96] * a1);
}

// ---------------- GAT layer 2 edge kernels (H=1, C=64) ----------------
__global__ void k_alpha2(const int* __restrict__ ei, const float* __restrict__ att,
                         int Eraw, int Etot) {
    int w = (blockIdx.x * blockDim.x + threadIdx.x) >> 5;
    if (w >= Etot) return;
    int lane = threadIdx.x & 31;
    int s, d;
    if (w < Eraw) { s = __ldg(&ei[w]); d = __ldg(&ei[Eraw + w]); } else { s = d = w - Eraw; }
    const float* xl = d_xl2 + (size_t)s * 64;
    const float* xr = d_xr2 + (size_t)d * 64;
    float p = 0.f;
    #pragma unroll
    for (int i = 0; i < 2; i++) {
        int c = lane + i * 32;
        float v = xl[c] + xr[c];
        v = v > 0.f ? v : 0.2f * v;
        p += v * att[c];
    }
    #pragma unroll
    for (int o = 16; o > 0; o >>= 1) p += __shfl_down_sync(0xFFFFFFFFu, p, o);
    if (lane == 0) {
        d_alpha2[w] = p;
        atomicMax(&d_amax2[d], fenc(p));
    }
}

__global__ void k_exp2(const int* __restrict__ ei, int Eraw, int Etot) {
    int e = blockIdx.x * blockDim.x + threadIdx.x;
    if (e >= Etot) return;
    int d = (e < Eraw) ? __ldg(&ei[Eraw + e]) : e - Eraw;
    float ex = __expf(d_alpha2[e] - fdec(d_amax2[d]));
    d_alpha2[e] = ex;
    atomicAdd(&d_denom2[d], ex);
}

__global__ void k_scat2(const int* __restrict__ ei, int Eraw, int Etot) {
    int w = (blockIdx.x * blockDim.x + threadIdx.x) >> 5;
    if (w >= Etot) return;
    int lane = threadIdx.x & 31;
    int s, d;
    if (w < Eraw) { s = __ldg(&ei[w]); d = __ldg(&ei[Eraw + w]); } else { s = d = w - Eraw; }
    float a = d_alpha2[w] / d_denom2[d];
    const float* xl = d_xl2 + (size_t)s * 64;
    float* op = d_h2 + (size_t)d * 64;
    atomicAdd(&op[lane],      xl[lane]      * a);
    atomicAdd(&op[lane + 32], xl[lane + 32] * a);
}

// ---------------- classifier: out = h2 @ Wc + bc ----------------
__global__ void k_cls(const float* __restrict__ Wc, const float* __restrict__ bc,
                      float* __restrict__ out) {
    int i = blockIdx.x * blockDim.x + threadIdx.x;
    if (i >= NN * 10) return;
    int n = i / 10, j = i % 10;
    const float* h = d_h2 + (size_t)n * 64;
    float acc = bc[j];
    #pragma unroll 16
    for (int k = 0; k < 64; k++) acc += h[k] * Wc[k * 10 + j];
    out[i] = acc;
}

// ---------------- launch ----------------
extern "C" void kernel_launch(void* const* d_in, const int* in_sizes, int n_in,
                              void* d_out, int out_size) {
    const float* x    = (const float*)d_in[0];
    const int*   ei   = (const int*)d_in[1];
    const float* c1w  = (const float*)d_in[2];
    const float* c1b  = (const float*)d_in[3];
    const float* c2w  = (const float*)d_in[4];
    const float* c2b  = (const float*)d_in[5];
    const float* Wl1  = (const float*)d_in[6];
    const float* bl1  = (const float*)d_in[7];
    const float* Wr1  = (const float*)d_in[8];
    const float* br1  = (const float*)d_in[9];
    const float* att1 = (const float*)d_in[10];
    const float* bias1= (const float*)d_in[11];
    const float* Wl2  = (const float*)d_in[12];
    const float* bl2  = (const float*)d_in[13];
    const float* Wr2  = (const float*)d_in[14];
    const float* br2  = (const float*)d_in[15];
    const float* att2 = (const float*)d_in[16];
    const float* bias2= (const float*)d_in[17];
    const float* Wc   = (const float*)d_in[18];
    const float* bc   = (const float*)d_in[19];
    float* out = (float*)d_out;

    int Eraw = in_sizes[1] / 2;
    int Etot = Eraw + NN;
    int edgeBlocks = (Etot + 7) / 8;   // warp per edge, 8 warps/block

    // CNN feature extractor
    k_conv1<<<NN, 256>>>(x, c1w, c1b);
    k_conv2<<<NN, 256>>>(c2w, c2b);

    // GAT layer 1
    k_gemm<0><<<dim3(2, NN / 64), 256>>>(Wl1, bl1, GIN, 128);
    k_gemm<1><<<dim3(2, NN / 64), 256>>>(Wr1, br1, GIN, 128);
    k_init1<<<(NN * 128 + 255) / 256, 256>>>(bias1);
    k_alpha1<<<edgeBlocks, 256>>>(ei, att1, Eraw, Etot);
    k_exp1<<<(Etot * 2 + 255) / 256, 256>>>(ei, Eraw, Etot);
    k_scat1<<<edgeBlocks, 256>>>(ei, Eraw, Etot);

    // GAT layer 2 (ReLU on h1 fused into the GEMM A-loads)
    k_gemm<2><<<dim3(1, NN / 64), 256>>>(Wl2, bl2, 128, 64);
    k_gemm<3><<<dim3(1, NN / 64), 256>>>(Wr2, br2, 128, 64);
    k_init2<<<(NN * 64 + 255) / 256, 256>>>(bias2);
    k_alpha2<<<edgeBlocks, 256>>>(ei, att2, Eraw, Etot);
    k_exp2<<<(Etot + 255) / 256, 256>>>(ei, Eraw, Etot);
    k_scat2<<<edgeBlocks, 256>>>(ei, Eraw, Etot);

    // classifier
    k_cls<<<(NN * 10 + 255) / 256, 256>>>(Wc, bc, out);
}

// round 3
// speedup vs baseline: 3.5617x; 3.5617x over previous
#include <cuda_runtime.h>
#include <math.h>

#define NN 16384
#define GIN 1568

// ---------------- scratch (static __device__, no allocation) ----------------
__device__ float d_c1buf[(size_t)NN * 16 * 14 * 14];   // conv1 pooled out  [N,16,14,14]
__device__ float d_h0[(size_t)NN * GIN];               // conv2 pooled flat [N,1568]
__device__ float d_xl1[(size_t)NN * 128];
__device__ float d_xr1[(size_t)NN * 128];
__device__ float d_h1[(size_t)NN * 128];
__device__ float d_xl2[(size_t)NN * 64];
__device__ float d_xr2[(size_t)NN * 64];
__device__ float d_h2[(size_t)NN * 64];
__device__ float d_alpha1[(size_t)(524288 + NN) * 2];
__device__ float d_alpha2[(size_t)(524288 + NN)];
__device__ unsigned d_amax1[NN * 2];
__device__ float d_denom1[NN * 2];
__device__ unsigned d_amax2[NN];
__device__ float d_denom2[NN];

// ---------------- helpers ----------------
__device__ __forceinline__ unsigned fenc(float f) {
    unsigned b = __float_as_uint(f);
    return b ^ ((b >> 31) ? 0xFFFFFFFFu : 0x80000000u);
}
__device__ __forceinline__ float fdec(unsigned u) {
    return __uint_as_float(u ^ ((u >> 31) ? 0x80000000u : 0xFFFFFFFFu));
}
#define ENC_NEG_INF 0x007FFFFFu   // fenc(-inf)

// ---------------- conv1 + relu + maxpool2 ----------------
// x [N,1,28,28] -> d_c1buf [N,16,14,14]
// Work item = (4-channel tile ct, pooled position pos). 784 items, 256 threads.
// 4x4 input patch in registers, weights broadcast from smem.
__global__ void k_conv1(const float* __restrict__ x,
                        const float* __restrict__ w,
                        const float* __restrict__ b) {
    __shared__ float sIn[784];
    __shared__ float sW[144];
    __shared__ float sB[16];
    int n = blockIdx.x, tid = threadIdx.x;
    const float* xp = x + (size_t)n * 784;
    for (int i = tid; i < 784; i += 256) sIn[i] = xp[i];
    if (tid < 144) sW[tid] = w[tid];
    if (tid < 16) sB[tid] = b[tid];
    __syncthreads();
    for (int item = tid; item < 784; item += 256) {
        int ct = item / 196;       // channel tile: channels ct*4 .. ct*4+3
        int pos = item % 196;
        int py = pos / 14, px = pos % 14;
        int y0 = 2 * py - 1, x0 = 2 * px - 1;
        float patch[4][4];
        #pragma unroll
        for (int r = 0; r < 4; r++) {
            int iy = y0 + r;
            bool okY = (unsigned)iy < 28u;
            #pragma unroll
            for (int cc = 0; cc < 4; cc++) {
                int ix = x0 + cc;
                patch[r][cc] = (okY && (unsigned)ix < 28u) ? sIn[iy * 28 + ix] : 0.f;
            }
        }
        float acc[4][4];
        #pragma unroll
        for (int c8 = 0; c8 < 4; c8++) {
            float bb = sB[ct * 4 + c8];
            acc[c8][0] = acc[c8][1] = acc[c8][2] = acc[c8][3] = bb;
        }
        #pragma unroll
        for (int c8 = 0; c8 < 4; c8++) {
            const float* wp = &sW[(ct * 4 + c8) * 9];
            #pragma unroll
            for (int ky = 0; ky < 3; ky++) {
                #pragma unroll
                for (int kx = 0; kx < 3; kx++) {
                    float wv = wp[ky * 3 + kx];
                    acc[c8][0] += patch[ky][kx]         * wv;
                    acc[c8][1] += patch[ky][kx + 1]     * wv;
                    acc[c8][2] += patch[ky + 1][kx]     * wv;
                    acc[c8][3] += patch[ky + 1][kx + 1] * wv;
                }
            }
        }
        #pragma unroll
        for (int c8 = 0; c8 < 4; c8++) {
            float best = fmaxf(fmaxf(acc[c8][0], acc[c8][1]), fmaxf(acc[c8][2], acc[c8][3]));
            d_c1buf[(size_t)n * 3136 + (ct * 4 + c8) * 196 + pos] = fmaxf(best, 0.f);
        }
    }
}

// ---------------- conv2 + relu + maxpool2 ----------------
// d_c1buf [N,16,14,14] -> d_h0 [N, 32*7*7 = 1568]
// Block = 1 image, 196 threads. Thread = (8-channel tile ct, pooled pos).
// Per input channel: 4x4 patch in regs, reused across 8 output channels;
// weights are warp-broadcast smem loads. 32 accumulators in regs.
__global__ void k_conv2(const float* __restrict__ w,
                        const float* __restrict__ b) {
    __shared__ float sIn[3136];
    __shared__ float sW[4608];
    __shared__ float sB[32];
    int n = blockIdx.x, tid = threadIdx.x;   // blockDim = 196
    const float* ip = d_c1buf + (size_t)n * 3136;
    for (int i = tid; i < 3136; i += 196) sIn[i] = ip[i];
    for (int i = tid; i < 4608; i += 196) sW[i] = __ldg(&w[i]);
    if (tid < 32) sB[tid] = b[tid];
    __syncthreads();

    int ct = tid / 49;         // 0..3 -> channels ct*8 .. ct*8+7
    int pos = tid % 49;
    int py = pos / 7, px = pos % 7;
    int y0 = 2 * py - 1, x0 = 2 * px - 1;

    float acc[8][4];
    #pragma unroll
    for (int c8 = 0; c8 < 8; c8++) {
        float bb = sB[ct * 8 + c8];
        acc[c8][0] = acc[c8][1] = acc[c8][2] = acc[c8][3] = bb;
    }
    for (int ci = 0; ci < 16; ci++) {
        float patch[4][4];
        const float* inp = &sIn[ci * 196];
        #pragma unroll
        for (int r = 0; r < 4; r++) {
            int iy = y0 + r;
            bool okY = (unsigned)iy < 14u;
            #pragma unroll
            for (int cc = 0; cc < 4; cc++) {
                int ix = x0 + cc;
                patch[r][cc] = (okY && (unsigned)ix < 14u) ? inp[iy * 14 + ix] : 0.f;
            }
        }
        #pragma unroll
        for (int c8 = 0; c8 < 8; c8++) {
            const float* wp = &sW[((ct * 8 + c8) * 16 + ci) * 9];
            #pragma unroll
            for (int ky = 0; ky < 3; ky++) {
                #pragma unroll
                for (int kx = 0; kx < 3; kx++) {
                    float wv = wp[ky * 3 + kx];
                    acc[c8][0] += patch[ky][kx]         * wv;
                    acc[c8][1] += patch[ky][kx + 1]     * wv;
                    acc[c8][2] += patch[ky + 1][kx]     * wv;
                    acc[c8][3] += patch[ky + 1][kx + 1] * wv;
                }
            }
        }
    }
    #pragma unroll
    for (int c8 = 0; c8 < 8; c8++) {
        float best = fmaxf(fmaxf(acc[c8][0], acc[c8][1]), fmaxf(acc[c8][2], acc[c8][3]));
        d_h0[(size_t)n * 1568 + (ct * 8 + c8) * 49 + pos] = fmaxf(best, 0.f);
    }
}

// ---------------- SGEMM: C = A(MxK) * B(KxNc) + bias ----------------
// 128x64 block tile, 8x4 per-thread microtile, BK=16, 256 threads.
// SEL: 0: A=d_h0,C=d_xl1 ; 1: A=d_h0,C=d_xr1 ; 2: A=relu(d_h1),C=d_xl2 ; 3: A=relu(d_h1),C=d_xr2
template <int SEL>
__global__ void k_gemm(const float* __restrict__ B,
                       const float* __restrict__ bias,
                       int K, int Nc) {
    const float* A = (SEL < 2) ? d_h0 : d_h1;
    float* C;
    if (SEL == 0) C = d_xl1;
    else if (SEL == 1) C = d_xr1;
    else if (SEL == 2) C = d_xl2;
    else C = d_xr2;

    __shared__ float As[16][128];
    __shared__ float Bs[16][64];
    int bm = blockIdx.y * 128, bn = blockIdx.x * 64;
    int tid = threadIdx.x;
    int ar = tid >> 1, ac = (tid & 1) << 3;   // A: row 0..127, col 0 or 8 (2 float4s)
    int br = tid >> 4, bc4 = (tid & 15) << 2; // B: row 0..15, col 4*(0..15)
    int ty = tid >> 4, tx = tid & 15;         // microtile: 8 rows, 4 cols
    float acc[8][4] = {};

    for (int k0 = 0; k0 < K; k0 += 16) {
        float4 a0 = *(const float4*)&A[(size_t)(bm + ar) * K + k0 + ac];
        float4 a1 = *(const float4*)&A[(size_t)(bm + ar) * K + k0 + ac + 4];
        if (SEL >= 2) {  // fused ReLU on layer-1 output
            a0.x = fmaxf(a0.x, 0.f); a0.y = fmaxf(a0.y, 0.f);
            a0.z = fmaxf(a0.z, 0.f); a0.w = fmaxf(a0.w, 0.f);
            a1.x = fmaxf(a1.x, 0.f); a1.y = fmaxf(a1.y, 0.f);
            a1.z = fmaxf(a1.z, 0.f); a1.w = fmaxf(a1.w, 0.f);
        }
        As[ac + 0][ar] = a0.x; As[ac + 1][ar] = a0.y;
        As[ac + 2][ar] = a0.z; As[ac + 3][ar] = a0.w;
        As[ac + 4][ar] = a1.x; As[ac + 5][ar] = a1.y;
        As[ac + 6][ar] = a1.z; As[ac + 7][ar] = a1.w;
        float4 bv = *(const float4*)&B[(size_t)(k0 + br) * Nc + bn + bc4];
        *(float4*)&Bs[br][bc4] = bv;
        __syncthreads();
        #pragma unroll
        for (int k = 0; k < 16; k++) {
            float a[8], bb[4];
            #pragma unroll
            for (int i = 0; i < 8; i++) a[i] = As[k][ty * 8 + i];
            #pragma unroll
            for (int j = 0; j < 4; j++) bb[j] = Bs[k][tx * 4 + j];
            #pragma unroll
            for (int i = 0; i < 8; i++)
                #pragma unroll
                for (int j = 0; j < 4; j++) acc[i][j] += a[i] * bb[j];
        }
        __syncthreads();
    }
    #pragma unroll
    for (int i = 0; i < 8; i++) {
        #pragma unroll
        for (int j = 0; j < 4; j++) {
            int row = bm + ty * 8 + i, col = bn + tx * 4 + j;
            C[(size_t)row * Nc + col] = acc[i][j] + bias[col];
        }
    }
}

// ---------------- init kernels ----------------
__global__ void k_init1(const float* __restrict__ bias1) {
    int i = blockIdx.x * blockDim.x + threadIdx.x;
    if (i < NN * 128) d_h1[i] = bias1[i & 127];
    if (i < NN * 2) { d_amax1[i] = ENC_NEG_INF; d_denom1[i] = 0.f; }
}
__global__ void k_init2(const float* __restrict__ bias2) {
    int i = blockIdx.x * blockDim.x + threadIdx.x;
    if (i < NN * 64) d_h2[i] = bias2[i & 63];
    if (i < NN) { d_amax2[i] = ENC_NEG_INF; d_denom2[i] = 0.f; }
}

// ---------------- GAT layer 1 edge kernels (H=2, C=64) ----------------
__global__ void k_alpha1(const int* __restrict__ ei, const float* __restrict__ att,
                         int Eraw, int Etot) {
    int w = (blockIdx.x * blockDim.x + threadIdx.x) >> 5;
    if (w >= Etot) return;
    int lane = threadIdx.x & 31;
    int s, d;
    if (w < Eraw) { s = __ldg(&ei[w]); d = __ldg(&ei[Eraw + w]); } else { s = d = w - Eraw; }
    const float* xl = d_xl1 + (size_t)s * 128;
    const float* xr = d_xr1 + (size_t)d * 128;
    float p0 = 0.f, p1 = 0.f;
    #pragma unroll
    for (int i = 0; i < 2; i++) {
        int c = lane + i * 32;
        float v = xl[c] + xr[c];
        v = v > 0.f ? v : 0.2f * v;
        p0 += v * att[c];
        int c2 = c + 64;
        float v2 = xl[c2] + xr[c2];
        v2 = v2 > 0.f ? v2 : 0.2f * v2;
        p1 += v2 * att[c2];
    }
    #pragma unroll
    for (int o = 16; o > 0; o >>= 1) {
        p0 += __shfl_down_sync(0xFFFFFFFFu, p0, o);
        p1 += __shfl_down_sync(0xFFFFFFFFu, p1, o);
    }
    if (lane == 0) {
        d_alpha1[(size_t)w * 2] = p0;
        d_alpha1[(size_t)w * 2 + 1] = p1;
        atomicMax(&d_amax1[d * 2], fenc(p0));
        atomicMax(&d_amax1[d * 2 + 1], fenc(p1));
    }
}

__global__ void k_exp1(const int* __restrict__ ei, int Eraw, int Etot) {
    int i = blockIdx.x * blockDim.x + threadIdx.x;
    if (i >= Etot * 2) return;
    int e = i >> 1, h = i & 1;
    int d = (e < Eraw) ? __ldg(&ei[Eraw + e]) : e - Eraw;
    float ex = __expf(d_alpha1[i] - fdec(d_amax1[d * 2 + h]));
    d_alpha1[i] = ex;
    atomicAdd(&d_denom1[d * 2 + h], ex);
}

__global__ void k_scat1(const int* __restrict__ ei, int Eraw, int Etot) {
    int w = (blockIdx.x * blockDim.x + threadIdx.x) >> 5;
    if (w >= Etot) return;
    int lane = threadIdx.x & 31;
    int s, d;
    if (w < Eraw) { s = __ldg(&ei[w]); d = __ldg(&ei[Eraw + w]); } else { s = d = w - Eraw; }
    float a0 = d_alpha1[(size_t)w * 2] / d_denom1[d * 2];
    float a1 = d_alpha1[(size_t)w * 2 + 1] / d_denom1[d * 2 + 1];
    const float* xl = d_xl1 + (size_t)s * 128;
    float* op = d_h1 + (size_t)d * 128;
    atomicAdd(&op[lane],      xl[lane]      * a0);
    atomicAdd(&op[lane + 32], xl[lane + 32] * a0);
    atomicAdd(&op[lane + 64], xl[lane + 64] * a1);
    atomicAdd(&op[lane + 96], xl[lane + 96] * a1);
}

// ---------------- GAT layer 2 edge kernels (H=1, C=64) ----------------
__global__ void k_alpha2(const int* __restrict__ ei, const float* __restrict__ att,
                         int Eraw, int Etot) {
    int w = (blockIdx.x * blockDim.x + threadIdx.x) >> 5;
    if (w >= Etot) return;
    int lane = threadIdx.x & 31;
    int s, d;
    if (w < Eraw) { s = __ldg(&ei[w]); d = __ldg(&ei[Eraw + w]); } else { s = d = w - Eraw; }
    const float* xl = d_xl2 + (size_t)s * 64;
    const float* xr = d_xr2 + (size_t)d * 64;
    float p = 0.f;
    #pragma unroll
    for (int i = 0; i < 2; i++) {
        int c = lane + i * 32;
        float v = xl[c] + xr[c];
        v = v > 0.f ? v : 0.2f * v;
        p += v * att[c];
    }
    #pragma unroll
    for (int o = 16; o > 0; o >>= 1) p += __shfl_down_sync(0xFFFFFFFFu, p, o);
    if (lane == 0) {
        d_alpha2[w] = p;
        atomicMax(&d_amax2[d], fenc(p));
    }
}

__global__ void k_exp2(const int* __restrict__ ei, int Eraw, int Etot) {
    int e = blockIdx.x * blockDim.x + threadIdx.x;
    if (e >= Etot) return;
    int d = (e < Eraw) ? __ldg(&ei[Eraw + e]) : e - Eraw;
    float ex = __expf(d_alpha2[e] - fdec(d_amax2[d]));
    d_alpha2[e] = ex;
    atomicAdd(&d_denom2[d], ex);
}

__global__ void k_scat2(const int* __restrict__ ei, int Eraw, int Etot) {
    int w = (blockIdx.x * blockDim.x + threadIdx.x) >> 5;
    if (w >= Etot) return;
    int lane = threadIdx.x & 31;
    int s, d;
    if (w < Eraw) { s = __ldg(&ei[w]); d = __ldg(&ei[Eraw + w]); } else { s = d = w - Eraw; }
    float a = d_alpha2[w] / d_denom2[d];
    const float* xl = d_xl2 + (size_t)s * 64;
    float* op = d_h2 + (size_t)d * 64;
    atomicAdd(&op[lane],      xl[lane]      * a);
    atomicAdd(&op[lane + 32], xl[lane + 32] * a);
}

// ---------------- classifier: out = h2 @ Wc + bc ----------------
__global__ void k_cls(const float* __restrict__ Wc, const float* __restrict__ bc,
                      float* __restrict__ out) {
    int i = blockIdx.x * blockDim.x + threadIdx.x;
    if (i >= NN * 10) return;
    int n = i / 10, j = i % 10;
    const float* h = d_h2 + (size_t)n * 64;
    float acc = bc[j];
    #pragma unroll 16
    for (int k = 0; k < 64; k++) acc += h[k] * Wc[k * 10 + j];
    out[i] = acc;
}

// ---------------- launch ----------------
extern "C" void kernel_launch(void* const* d_in, const int* in_sizes, int n_in,
                              void* d_out, int out_size) {
    const float* x    = (const float*)d_in[0];
    const int*   ei   = (const int*)d_in[1];
    const float* c1w  = (const float*)d_in[2];
    const float* c1b  = (const float*)d_in[3];
    const float* c2w  = (const float*)d_in[4];
    const float* c2b  = (const float*)d_in[5];
    const float* Wl1  = (const float*)d_in[6];
    const float* bl1  = (const float*)d_in[7];
    const float* Wr1  = (const float*)d_in[8];
    const float* br1  = (const float*)d_in[9];
    const float* att1 = (const float*)d_in[10];
    const float* bias1= (const float*)d_in[11];
    const float* Wl2  = (const float*)d_in[12];
    const float* bl2  = (const float*)d_in[13];
    const float* Wr2  = (const float*)d_in[14];
    const float* br2  = (const float*)d_in[15];
    const float* att2 = (const float*)d_in[16];
    const float* bias2= (const float*)d_in[17];
    const float* Wc   = (const float*)d_in[18];
    const float* bc   = (const float*)d_in[19];
    float* out = (float*)d_out;

    int Eraw = in_sizes[1] / 2;
    int Etot = Eraw + NN;
    int edgeBlocks = (Etot + 7) / 8;   // warp per edge, 8 warps/block

    // CNN feature extractor
    k_conv1<<<NN, 256>>>(x, c1w, c1b);
    k_conv2<<<NN, 196>>>(c2w, c2b);

    // GAT layer 1
    k_gemm<0><<<dim3(2, NN / 128), 256>>>(Wl1, bl1, GIN, 128);
    k_gemm<1><<<dim3(2, NN / 128), 256>>>(Wr1, br1, GIN, 128);
    k_init1<<<(NN * 128 + 255) / 256, 256>>>(bias1);
    k_alpha1<<<edgeBlocks, 256>>>(ei, att1, Eraw, Etot);
    k_exp1<<<(Etot * 2 + 255) / 256, 256>>>(ei, Eraw, Etot);
    k_scat1<<<edgeBlocks, 256>>>(ei, Eraw, Etot);

    // GAT layer 2 (ReLU on h1 fused into the GEMM A-loads)
    k_gemm<2><<<dim3(1, NN / 128), 256>>>(Wl2, bl2, 128, 64);
    k_gemm<3><<<dim3(1, NN / 128), 256>>>(Wr2, br2, 128, 64);
    k_init2<<<(NN * 64 + 255) / 256, 256>>>(bias2);
    k_alpha2<<<edgeBlocks, 256>>>(ei, att2, Eraw, Etot);
    k_exp2<<<(Etot + 255) / 256, 256>>>(ei, Eraw, Etot);
    k_scat2<<<edgeBlocks, 256>>>(ei, Eraw, Etot);

    // classifier
    k_cls<<<(NN * 10 + 255) / 256, 256>>>(Wc, bc, out);
}

// round 5
// speedup vs baseline: 3.8338x; 1.0764x over previous
#include <cuda_runtime.h>
#include <math.h>

#define NN 16384
#define GIN 1568
#define EMAX 540672   // 524288 + NN

// ---------------- scratch (static __device__, no allocation) ----------------
__device__ float d_c1buf[(size_t)NN * 16 * 14 * 14];
__device__ float d_h0[(size_t)NN * GIN];
__device__ float d_xl1[(size_t)NN * 128];
__device__ float d_xr1[(size_t)NN * 128];
__device__ float d_h1[(size_t)NN * 128];
__device__ float d_xl2[(size_t)NN * 64];
__device__ float d_xr2[(size_t)NN * 64];
__device__ float d_h2[(size_t)NN * 64];
__device__ int d_deg[NN];
__device__ int d_rowstart[NN + 1];
__device__ int d_cursor[NN];
__device__ int d_csrc[EMAX];

// ---------------- conv1 + relu + maxpool2 ----------------
__global__ void k_conv1(const float* __restrict__ x,
                        const float* __restrict__ w,
                        const float* __restrict__ b) {
    __shared__ float sIn[784];
    __shared__ float sW[144];
    __shared__ float sB[16];
    int n = blockIdx.x, tid = threadIdx.x;
    const float* xp = x + (size_t)n * 784;
    for (int i = tid; i < 784; i += 256) sIn[i] = xp[i];
    if (tid < 144) sW[tid] = w[tid];
    if (tid < 16) sB[tid] = b[tid];
    __syncthreads();
    for (int item = tid; item < 784; item += 256) {
        int ct = item / 196;
        int pos = item % 196;
        int py = pos / 14, px = pos % 14;
        int y0 = 2 * py - 1, x0 = 2 * px - 1;
        float patch[4][4];
        #pragma unroll
        for (int r = 0; r < 4; r++) {
            int iy = y0 + r;
            bool okY = (unsigned)iy < 28u;
            #pragma unroll
            for (int cc = 0; cc < 4; cc++) {
                int ix = x0 + cc;
                patch[r][cc] = (okY && (unsigned)ix < 28u) ? sIn[iy * 28 + ix] : 0.f;
            }
        }
        float acc[4][4];
        #pragma unroll
        for (int c8 = 0; c8 < 4; c8++) {
            float bb = sB[ct * 4 + c8];
            acc[c8][0] = acc[c8][1] = acc[c8][2] = acc[c8][3] = bb;
        }
        #pragma unroll
        for (int c8 = 0; c8 < 4; c8++) {
            const float* wp = &sW[(ct * 4 + c8) * 9];
            #pragma unroll
            for (int ky = 0; ky < 3; ky++) {
                #pragma unroll
                for (int kx = 0; kx < 3; kx++) {
                    float wv = wp[ky * 3 + kx];
                    acc[c8][0] += patch[ky][kx]         * wv;
                    acc[c8][1] += patch[ky][kx + 1]     * wv;
                    acc[c8][2] += patch[ky + 1][kx]     * wv;
                    acc[c8][3] += patch[ky + 1][kx + 1] * wv;
                }
            }
        }
        #pragma unroll
        for (int c8 = 0; c8 < 4; c8++) {
            float best = fmaxf(fmaxf(acc[c8][0], acc[c8][1]), fmaxf(acc[c8][2], acc[c8][3]));
            d_c1buf[(size_t)n * 3136 + (ct * 4 + c8) * 196 + pos] = fmaxf(best, 0.f);
        }
    }
}

// ---------------- conv2 + relu + maxpool2 ----------------
__global__ void k_conv2(const float* __restrict__ w,
                        const float* __restrict__ b) {
    __shared__ float sIn[3136];
    __shared__ float sW[4608];
    __shared__ float sB[32];
    int n = blockIdx.x, tid = threadIdx.x;   // blockDim = 196
    const float* ip = d_c1buf + (size_t)n * 3136;
    for (int i = tid; i < 3136; i += 196) sIn[i] = ip[i];
    for (int i = tid; i < 4608; i += 196) sW[i] = __ldg(&w[i]);
    if (tid < 32) sB[tid] = b[tid];
    __syncthreads();

    int ct = tid / 49;
    int pos = tid % 49;
    int py = pos / 7, px = pos % 7;
    int y0 = 2 * py - 1, x0 = 2 * px - 1;

    float acc[8][4];
    #pragma unroll
    for (int c8 = 0; c8 < 8; c8++) {
        float bb = sB[ct * 8 + c8];
        acc[c8][0] = acc[c8][1] = acc[c8][2] = acc[c8][3] = bb;
    }
    for (int ci = 0; ci < 16; ci++) {
        float patch[4][4];
        const float* inp = &sIn[ci * 196];
        #pragma unroll
        for (int r = 0; r < 4; r++) {
            int iy = y0 + r;
            bool okY = (unsigned)iy < 14u;
            #pragma unroll
            for (int cc = 0; cc < 4; cc++) {
                int ix = x0 + cc;
                patch[r][cc] = (okY && (unsigned)ix < 14u) ? inp[iy * 14 + ix] : 0.f;
            }
        }
        #pragma unroll
        for (int c8 = 0; c8 < 8; c8++) {
            const float* wp = &sW[((ct * 8 + c8) * 16 + ci) * 9];
            #pragma unroll
            for (int ky = 0; ky < 3; ky++) {
                #pragma unroll
                for (int kx = 0; kx < 3; kx++) {
                    float wv = wp[ky * 3 + kx];
                    acc[c8][0] += patch[ky][kx]         * wv;
                    acc[c8][1] += patch[ky][kx + 1]     * wv;
                    acc[c8][2] += patch[ky + 1][kx]     * wv;
                    acc[c8][3] += patch[ky + 1][kx + 1] * wv;
                }
            }
        }
    }
    #pragma unroll
    for (int c8 = 0; c8 < 8; c8++) {
        float best = fmaxf(fmaxf(acc[c8][0], acc[c8][1]), fmaxf(acc[c8][2], acc[c8][3]));
        d_h0[(size_t)n * 1568 + (ct * 8 + c8) * 49 + pos] = fmaxf(best, 0.f);
    }
}

// ---------------- SGEMM: 64x64 tile, BK=16, 4x4 microtile, 256 threads ----------------
// SEL: 0: A=d_h0,C=d_xl1 ; 1: A=d_h0,C=d_xr1 ; 2: A=relu(d_h1),C=d_xl2 ; 3: A=relu(d_h1),C=d_xr2
template <int SEL>
__global__ void k_gemm(const float* __restrict__ B,
                       const float* __restrict__ bias,
                       int K, int Nc) {
    const float* A = (SEL < 2) ? d_h0 : d_h1;
    float* C;
    if (SEL == 0) C = d_xl1;
    else if (SEL == 1) C = d_xr1;
    else if (SEL == 2) C = d_xl2;
    else C = d_xr2;

    __shared__ float As[16][64];
    __shared__ float Bs[16][64];
    int bm = blockIdx.y * 64, bn = blockIdx.x * 64;
    int tid = threadIdx.x;
    int ar = tid >> 2, ac = (tid & 3) << 2;   // A: 64 rows x 16 k
    int br = tid >> 4, bc4 = (tid & 15) << 2; // B: 16 k x 64 cols
    int ty = tid >> 4, tx = tid & 15;         // 4x4 microtile
    float acc[4][4] = {};

    for (int k0 = 0; k0 < K; k0 += 16) {
        float4 av = *(const float4*)&A[(size_t)(bm + ar) * K + k0 + ac];
        if (SEL >= 2) {
            av.x = fmaxf(av.x, 0.f); av.y = fmaxf(av.y, 0.f);
            av.z = fmaxf(av.z, 0.f); av.w = fmaxf(av.w, 0.f);
        }
        As[ac + 0][ar] = av.x; As[ac + 1][ar] = av.y;
        As[ac + 2][ar] = av.z; As[ac + 3][ar] = av.w;
        *(float4*)&Bs[br][bc4] = *(const float4*)&B[(size_t)(k0 + br) * Nc + bn + bc4];
        __syncthreads();
        #pragma unroll
        for (int k = 0; k < 16; k++) {
            float4 a4 = *(const float4*)&As[k][ty * 4];
            float4 b4 = *(const float4*)&Bs[k][tx * 4];
            acc[0][0] += a4.x * b4.x; acc[0][1] += a4.x * b4.y;
            acc[0][2] += a4.x * b4.z; acc[0][3] += a4.x * b4.w;
            acc[1][0] += a4.y * b4.x; acc[1][1] += a4.y * b4.y;
            acc[1][2] += a4.y * b4.z; acc[1][3] += a4.y * b4.w;
            acc[2][0] += a4.z * b4.x; acc[2][1] += a4.z * b4.y;
            acc[2][2] += a4.z * b4.z; acc[2][3] += a4.z * b4.w;
            acc[3][0] += a4.w * b4.x; acc[3][1] += a4.w * b4.y;
            acc[3][2] += a4.w * b4.z; acc[3][3] += a4.w * b4.w;
        }
        __syncthreads();
    }
    float4 bv = *(const float4*)&bias[bn + tx * 4];
    #pragma unroll
    for (int i = 0; i < 4; i++) {
        int row = bm + ty * 4 + i;
        float4 o;
        o.x = acc[i][0] + bv.x; o.y = acc[i][1] + bv.y;
        o.z = acc[i][2] + bv.z; o.w = acc[i][3] + bv.w;
        *(float4*)&C[(size_t)row * Nc + bn + tx * 4] = o;
    }
}

// ---------------- CSR build ----------------
__global__ void k_deg_init() {
    int i = blockIdx.x * blockDim.x + threadIdx.x;
    if (i < NN) d_deg[i] = 1;   // self loop
}
__global__ void k_hist(const int* __restrict__ ei, int Eraw) {
    int i = blockIdx.x * blockDim.x + threadIdx.x;
    if (i < Eraw) atomicAdd(&d_deg[__ldg(&ei[Eraw + i])], 1);
}
__global__ void k_scan() {   // 1 block, 1024 threads, 16 elems each
    __shared__ int sP[1024];
    int tid = threadIdx.x;
    int base = tid * 16;
    int local[16];
    int run = 0;
    #pragma unroll
    for (int i = 0; i < 16; i++) { local[i] = run; run += d_deg[base + i]; }
    sP[tid] = run;
    __syncthreads();
    for (int off = 1; off < 1024; off <<= 1) {
        int v = (tid >= off) ? sP[tid - off] : 0;
        __syncthreads();
        sP[tid] += v;
        __syncthreads();
    }
    int pre = (tid == 0) ? 0 : sP[tid - 1];
    #pragma unroll
    for (int i = 0; i < 16; i++) {
        int n = base + i;
        int rs = pre + local[i];
        d_rowstart[n] = rs;
        d_cursor[n] = rs + 1;   // slot 0 = self loop
        d_csrc[rs] = n;
    }
    if (tid == 1023) d_rowstart[NN] = sP[1023];
}
__global__ void k_scatter(const int* __restrict__ ei, int Eraw) {
    int i = blockIdx.x * blockDim.x + threadIdx.x;
    if (i >= Eraw) return;
    int s = __ldg(&ei[i]), d = __ldg(&ei[Eraw + i]);
    int pos = atomicAdd(&d_cursor[d], 1);
    d_csrc[pos] = s;
}

// ---------------- fused GAT layer 1 (H=2, C=64): warp per dst node ----------------
__global__ void k_gat1(const float* __restrict__ att, const float* __restrict__ bias1) {
    int w = (blockIdx.x * blockDim.x + threadIdx.x) >> 5;
    if (w >= NN) return;
    int lane = threadIdx.x & 31;
    float aA = att[lane], aB = att[lane + 32], aC = att[lane + 64], aD = att[lane + 96];
    const float* xr = d_xr1 + (size_t)w * 128;
    float r0 = xr[lane], r1 = xr[lane + 32], r2 = xr[lane + 64], r3 = xr[lane + 96];
    float acc0 = 0.f, acc1 = 0.f, acc2 = 0.f, acc3 = 0.f, s0 = 0.f, s1 = 0.f;
    int beg = d_rowstart[w], end = d_rowstart[w + 1];
    for (int i = beg; i < end; i++) {
        int s = d_csrc[i];
        const float* xl = d_xl1 + (size_t)s * 128;
        float v0 = xl[lane], v1 = xl[lane + 32], v2 = xl[lane + 64], v3 = xl[lane + 96];
        float t0 = v0 + r0; t0 = t0 > 0.f ? t0 : 0.2f * t0;
        float t1 = v1 + r1; t1 = t1 > 0.f ? t1 : 0.2f * t1;
        float t2 = v2 + r2; t2 = t2 > 0.f ? t2 : 0.2f * t2;
        float t3 = v3 + r3; t3 = t3 > 0.f ? t3 : 0.2f * t3;
        float p0 = t0 * aA + t1 * aB;
        float p1 = t2 * aC + t3 * aD;
        #pragma unroll
        for (int o = 16; o > 0; o >>= 1) {
            p0 += __shfl_xor_sync(0xFFFFFFFFu, p0, o);
            p1 += __shfl_xor_sync(0xFFFFFFFFu, p1, o);
        }
        float e0 = __expf(p0), e1 = __expf(p1);
        s0 += e0; s1 += e1;
        acc0 += e0 * v0; acc1 += e0 * v1; acc2 += e1 * v2; acc3 += e1 * v3;
    }
    float* o = d_h1 + (size_t)w * 128;
    float i0 = 1.f / s0, i1 = 1.f / s1;
    o[lane]      = bias1[lane]      + acc0 * i0;
    o[lane + 32] = bias1[lane + 32] + acc1 * i0;
    o[lane + 64] = bias1[lane + 64] + acc2 * i1;
    o[lane + 96] = bias1[lane + 96] + acc3 * i1;
}

// ---------------- fused GAT layer 2 (H=1, C=64): warp per dst node ----------------
__global__ void k_gat2(const float* __restrict__ att, const float* __restrict__ bias2) {
    int w = (blockIdx.x * blockDim.x + threadIdx.x) >> 5;
    if (w >= NN) return;
    int lane = threadIdx.x & 31;
    float aA = att[lane], aB = att[lane + 32];
    const float* xr = d_xr2 + (size_t)w * 64;
    float r0 = xr[lane], r1 = xr[lane + 32];
    float acc0 = 0.f, acc1 = 0.f, s0 = 0.f;
    int beg = d_rowstart[w], end = d_rowstart[w + 1];
    for (int i = beg; i < end; i++) {
        int s = d_csrc[i];
        const float* xl = d_xl2 + (size_t)s * 64;
        float v0 = xl[lane], v1 = xl[lane + 32];
        float t0 = v0 + r0; t0 = t0 > 0.f ? t0 : 0.2f * t0;
        float t1 = v1 + r1; t1 = t1 > 0.f ? t1 : 0.2f * t1;
        float p = t0 * aA + t1 * aB;
        #pragma unroll
        for (int o = 16; o > 0; o >>= 1) p += __shfl_xor_sync(0xFFFFFFFFu, p, o);
        float e = __expf(p);
        s0 += e;
        acc0 += e * v0; acc1 += e * v1;
    }
    float* o = d_h2 + (size_t)w * 64;
    float inv = 1.f / s0;
    o[lane]      = bias2[lane]      + acc0 * inv;
    o[lane + 32] = bias2[lane + 32] + acc1 * inv;
}

// ---------------- classifier: out = h2 @ Wc + bc ----------------
__global__ void k_cls(const float* __restrict__ Wc, const float* __restrict__ bc,
                      float* __restrict__ out) {
    int i = blockIdx.x * blockDim.x + threadIdx.x;
    if (i >= NN * 10) return;
    int n = i / 10, j = i % 10;
    const float* h = d_h2 + (size_t)n * 64;
    float acc = bc[j];
    #pragma unroll 16
    for (int k = 0; k < 64; k++) acc += h[k] * Wc[k * 10 + j];
    out[i] = acc;
}

// ---------------- launch ----------------
extern "C" void kernel_launch(void* const* d_in, const int* in_sizes, int n_in,
                              void* d_out, int out_size) {
    const float* x    = (const float*)d_in[0];
    const int*   ei   = (const int*)d_in[1];
    const float* c1w  = (const float*)d_in[2];
    const float* c1b  = (const float*)d_in[3];
    const float* c2w  = (const float*)d_in[4];
    const float* c2b  = (const float*)d_in[5];
    const float* Wl1  = (const float*)d_in[6];
    const float* bl1  = (const float*)d_in[7];
    const float* Wr1  = (const float*)d_in[8];
    const float* br1  = (const float*)d_in[9];
    const float* att1 = (const float*)d_in[10];
    const float* bias1= (const float*)d_in[11];
    const float* Wl2  = (const float*)d_in[12];
    const float* bl2  = (const float*)d_in[13];
    const float* Wr2  = (const float*)d_in[14];
    const float* br2  = (const float*)d_in[15];
    const float* att2 = (const float*)d_in[16];
    const float* bias2= (const float*)d_in[17];
    const float* Wc   = (const float*)d_in[18];
    const float* bc   = (const float*)d_in[19];
    float* out = (float*)d_out;

    int Eraw = in_sizes[1] / 2;
    int nodeBlocks = NN / 8;   // warp per node, 8 warps/block

    // CSR build (order preserved within the stream)
    k_deg_init<<<NN / 256, 256>>>();
    k_hist<<<(Eraw + 255) / 256, 256>>>(ei, Eraw);
    k_scan<<<1, 1024>>>();
    k_scatter<<<(Eraw + 255) / 256, 256>>>(ei, Eraw);

    // CNN feature extractor
    k_conv1<<<NN, 256>>>(x, c1w, c1b);
    k_conv2<<<NN, 196>>>(c2w, c2b);

    // GAT layer 1
    k_gemm<0><<<dim3(2, NN / 64), 256>>>(Wl1, bl1, GIN, 128);
    k_gemm<1><<<dim3(2, NN / 64), 256>>>(Wr1, br1, GIN, 128);
    k_gat1<<<nodeBlocks, 256>>>(att1, bias1);

    // GAT layer 2 (ReLU on h1 fused into GEMM A-loads)
    k_gemm<2><<<dim3(1, NN / 64), 256>>>(Wl2, bl2, 128, 64);
    k_gemm<3><<<dim3(1, NN / 64), 256>>>(Wr2, br2, 128, 64);
    k_gat2<<<nodeBlocks, 256>>>(att2, bias2);

    // classifier
    k_cls<<<(NN * 10 + 255) / 256, 256>>>(Wc, bc, out);
}

// round 7
// speedup vs baseline: 4.3684x; 1.1395x over previous
#include <cuda_runtime.h>
#include <math.h>

#define NN 16384
#define GIN 1568
#define EMAX 540672   // 524288 + NN

// ---------------- scratch (static __device__, no allocation) ----------------
__device__ float d_c1buf[(size_t)NN * 16 * 14 * 14];
__device__ float d_h0[(size_t)NN * GIN];
__device__ float d_xl1[(size_t)NN * 128];
__device__ float d_xr1[(size_t)NN * 128];
__device__ float d_h1[(size_t)NN * 128];
__device__ float d_xl2[(size_t)NN * 64];
__device__ float d_xr2[(size_t)NN * 64];
__device__ float d_h2[(size_t)NN * 64];
__device__ int d_deg[NN];
__device__ int d_rowstart[NN + 1];
__device__ int d_cursor[NN];
__device__ int d_csrc[EMAX];

// ---------------- tf32 helpers ----------------
__device__ __forceinline__ unsigned f2tf32(float x) {
    unsigned u;
    asm("cvt.rna.tf32.f32 %0, %1;" : "=r"(u) : "f"(x));
    return u;
}
__device__ __forceinline__ void mma_tf32(float* d, const unsigned* a, const unsigned* b) {
    asm volatile(
        "mma.sync.aligned.m16n8k8.row.col.f32.tf32.tf32.f32 "
        "{%0,%1,%2,%3}, {%4,%5,%6,%7}, {%8,%9}, {%0,%1,%2,%3};\n"
        : "+f"(d[0]), "+f"(d[1]), "+f"(d[2]), "+f"(d[3])
        : "r"(a[0]), "r"(a[1]), "r"(a[2]), "r"(a[3]), "r"(b[0]), "r"(b[1]));
}

// ---------------- conv1 + relu + maxpool2 ----------------
__global__ void k_conv1(const float* __restrict__ x,
                        const float* __restrict__ w,
                        const float* __restrict__ b) {
    __shared__ float sIn[784];
    __shared__ float sW[144];
    __shared__ float sB[16];
    int n = blockIdx.x, tid = threadIdx.x;
    const float* xp = x + (size_t)n * 784;
    for (int i = tid; i < 784; i += 256) sIn[i] = xp[i];
    if (tid < 144) sW[tid] = w[tid];
    if (tid < 16) sB[tid] = b[tid];
    __syncthreads();
    for (int item = tid; item < 784; item += 256) {
        int ct = item / 196;
        int pos = item % 196;
        int py = pos / 14, px = pos % 14;
        int y0 = 2 * py - 1, x0 = 2 * px - 1;
        float patch[4][4];
        #pragma unroll
        for (int r = 0; r < 4; r++) {
            int iy = y0 + r;
            bool okY = (unsigned)iy < 28u;
            #pragma unroll
            for (int cc = 0; cc < 4; cc++) {
                int ix = x0 + cc;
                patch[r][cc] = (okY && (unsigned)ix < 28u) ? sIn[iy * 28 + ix] : 0.f;
            }
        }
        float acc[4][4];
        #pragma unroll
        for (int c8 = 0; c8 < 4; c8++) {
            float bb = sB[ct * 4 + c8];
            acc[c8][0] = acc[c8][1] = acc[c8][2] = acc[c8][3] = bb;
        }
        #pragma unroll
        for (int c8 = 0; c8 < 4; c8++) {
            const float* wp = &sW[(ct * 4 + c8) * 9];
            #pragma unroll
            for (int ky = 0; ky < 3; ky++) {
                #pragma unroll
                for (int kx = 0; kx < 3; kx++) {
                    float wv = wp[ky * 3 + kx];
                    acc[c8][0] += patch[ky][kx]         * wv;
                    acc[c8][1] += patch[ky][kx + 1]     * wv;
                    acc[c8][2] += patch[ky + 1][kx]     * wv;
                    acc[c8][3] += patch[ky + 1][kx + 1] * wv;
                }
            }
        }
        #pragma unroll
        for (int c8 = 0; c8 < 4; c8++) {
            float best = fmaxf(fmaxf(acc[c8][0], acc[c8][1]), fmaxf(acc[c8][2], acc[c8][3]));
            d_c1buf[(size_t)n * 3136 + (ct * 4 + c8) * 196 + pos] = fmaxf(best, 0.f);
        }
    }
}

// ---------------- conv2 + relu + maxpool2 ----------------
__global__ void k_conv2(const float* __restrict__ w,
                        const float* __restrict__ b) {
    __shared__ float sIn[3136];
    __shared__ float sW[4608];
    __shared__ float sB[32];
    int n = blockIdx.x, tid = threadIdx.x;   // blockDim = 196
    const float* ip = d_c1buf + (size_t)n * 3136;
    for (int i = tid; i < 3136; i += 196) sIn[i] = ip[i];
    for (int i = tid; i < 4608; i += 196) sW[i] = __ldg(&w[i]);
    if (tid < 32) sB[tid] = b[tid];
    __syncthreads();

    int ct = tid / 49;
    int pos = tid % 49;
    int py = pos / 7, px = pos % 7;
    int y0 = 2 * py - 1, x0 = 2 * px - 1;

    float acc[8][4];
    #pragma unroll
    for (int c8 = 0; c8 < 8; c8++) {
        float bb = sB[ct * 8 + c8];
        acc[c8][0] = acc[c8][1] = acc[c8][2] = acc[c8][3] = bb;
    }
    for (int ci = 0; ci < 16; ci++) {
        float patch[4][4];
        const float* inp = &sIn[ci * 196];
        #pragma unroll
        for (int r = 0; r < 4; r++) {
            int iy = y0 + r;
            bool okY = (unsigned)iy < 14u;
            #pragma unroll
            for (int cc = 0; cc < 4; cc++) {
                int ix = x0 + cc;
                patch[r][cc] = (okY && (unsigned)ix < 14u) ? inp[iy * 14 + ix] : 0.f;
            }
        }
        #pragma unroll
        for (int c8 = 0; c8 < 8; c8++) {
            const float* wp = &sW[((ct * 8 + c8) * 16 + ci) * 9];
            #pragma unroll
            for (int ky = 0; ky < 3; ky++) {
                #pragma unroll
                for (int kx = 0; kx < 3; kx++) {
                    float wv = wp[ky * 3 + kx];
                    acc[c8][0] += patch[ky][kx]         * wv;
                    acc[c8][1] += patch[ky][kx + 1]     * wv;
                    acc[c8][2] += patch[ky + 1][kx]     * wv;
                    acc[c8][3] += patch[ky + 1][kx + 1] * wv;
                }
            }
        }
    }
    #pragma unroll
    for (int c8 = 0; c8 < 8; c8++) {
        float best = fmaxf(fmaxf(acc[c8][0], acc[c8][1]), fmaxf(acc[c8][2], acc[c8][3]));
        d_h0[(size_t)n * 1568 + (ct * 8 + c8) * 49 + pos] = fmaxf(best, 0.f);
    }
}

// ---------------- tf32 tensor-core GEMM: C = A(MxK)*B(KxNc) + bias ----------------
// Block tile 128x64, BK=16, 8 warps; warp = 32x32 (2 m16 x 4 n8 mma tiles).
// SEL: 0: A=d_h0,C=d_xl1 ; 1: A=d_h0,C=d_xr1 ; 2: A=relu(d_h1),C=d_xl2 ; 3: A=relu(d_h1),C=d_xr2
template <int SEL>
__global__ void k_gemm(const float* __restrict__ B,
                       const float* __restrict__ bias,
                       int K, int Nc) {
    const float* A = (SEL < 2) ? d_h0 : d_h1;
    float* C;
    if (SEL == 0) C = d_xl1;
    else if (SEL == 1) C = d_xr1;
    else if (SEL == 2) C = d_xl2;
    else C = d_xr2;

    __shared__ unsigned As[16][132];   // [k][m], padded
    __shared__ unsigned Bs[16][68];    // [k][n], padded

    int bm = blockIdx.y * 128, bn = blockIdx.x * 64;
    int tid = threadIdx.x;
    int warp = tid >> 5, lane = tid & 31;
    int g = lane >> 2, t = lane & 3;
    int mW = (warp >> 1) * 32, nW = (warp & 1) * 32;

    // staging indices
    int arow = tid >> 1;            // 0..127
    int akc = (tid & 1) * 8;        // 0 or 8
    int bkr = tid >> 4;             // 0..15
    int bnc = (tid & 15) * 4;       // 0..60

    float acc[2][4][4] = {};

    for (int k0 = 0; k0 < K; k0 += 16) {
        // stage A: 128 rows x 16 k (transposed into As[k][m]), tf32-converted
        const float* ap = &A[(size_t)(bm + arow) * K + k0 + akc];
        float4 av0 = *(const float4*)ap;
        float4 av1 = *(const float4*)(ap + 4);
        if (SEL >= 2) {
            av0.x = fmaxf(av0.x, 0.f); av0.y = fmaxf(av0.y, 0.f);
            av0.z = fmaxf(av0.z, 0.f); av0.w = fmaxf(av0.w, 0.f);
            av1.x = fmaxf(av1.x, 0.f); av1.y = fmaxf(av1.y, 0.f);
            av1.z = fmaxf(av1.z, 0.f); av1.w = fmaxf(av1.w, 0.f);
        }
        As[akc + 0][arow] = f2tf32(av0.x); As[akc + 1][arow] = f2tf32(av0.y);
        As[akc + 2][arow] = f2tf32(av0.z); As[akc + 3][arow] = f2tf32(av0.w);
        As[akc + 4][arow] = f2tf32(av1.x); As[akc + 5][arow] = f2tf32(av1.y);
        As[akc + 6][arow] = f2tf32(av1.z); As[akc + 7][arow] = f2tf32(av1.w);
        // stage B: 16 k x 64 n
        float4 bv = *(const float4*)&B[(size_t)(k0 + bkr) * Nc + bn + bnc];
        Bs[bkr][bnc + 0] = f2tf32(bv.x); Bs[bkr][bnc + 1] = f2tf32(bv.y);
        Bs[bkr][bnc + 2] = f2tf32(bv.z); Bs[bkr][bnc + 3] = f2tf32(bv.w);
        __syncthreads();

        #pragma unroll
        for (int kc = 0; kc < 2; kc++) {
            int kb = kc * 8;
            unsigned a[2][4], bfr[4][2];
            #pragma unroll
            for (int mi = 0; mi < 2; mi++) {
                int mrow = mW + mi * 16;
                a[mi][0] = As[kb + t][mrow + g];
                a[mi][1] = As[kb + t][mrow + g + 8];
                a[mi][2] = As[kb + t + 4][mrow + g];
                a[mi][3] = As[kb + t + 4][mrow + g + 8];
            }
            #pragma unroll
            for (int ni = 0; ni < 4; ni++) {
                bfr[ni][0] = Bs[kb + t][nW + ni * 8 + g];
                bfr[ni][1] = Bs[kb + t + 4][nW + ni * 8 + g];
            }
            #pragma unroll
            for (int mi = 0; mi < 2; mi++)
                #pragma unroll
                for (int ni = 0; ni < 4; ni++)
                    mma_tf32(acc[mi][ni], a[mi], bfr[ni]);
        }
        __syncthreads();
    }

    // epilogue: d-frag element (g + {0,8}, 2t + {0,1}) per tile
    #pragma unroll
    for (int mi = 0; mi < 2; mi++) {
        int row0 = bm + mW + mi * 16 + g;
        #pragma unroll
        for (int ni = 0; ni < 4; ni++) {
            int col = bn + nW + ni * 8 + t * 2;
            float b0 = bias[col], b1 = bias[col + 1];
            C[(size_t)row0 * Nc + col]           = acc[mi][ni][0] + b0;
            C[(size_t)row0 * Nc + col + 1]       = acc[mi][ni][1] + b1;
            C[(size_t)(row0 + 8) * Nc + col]     = acc[mi][ni][2] + b0;
            C[(size_t)(row0 + 8) * Nc + col + 1] = acc[mi][ni][3] + b1;
        }
    }
}

// ---------------- CSR build ----------------
__global__ void k_deg_init() {
    int i = blockIdx.x * blockDim.x + threadIdx.x;
    if (i < NN) d_deg[i] = 1;   // self loop
}
__global__ void k_hist(const int* __restrict__ ei, int Eraw) {
    int i = blockIdx.x * blockDim.x + threadIdx.x;
    if (i < Eraw) atomicAdd(&d_deg[__ldg(&ei[Eraw + i])], 1);
}
__global__ void k_scan() {   // 1 block, 1024 threads, 16 elems each
    __shared__ int sP[1024];
    int tid = threadIdx.x;
    int base = tid * 16;
    int local[16];
    int run = 0;
    #pragma unroll
    for (int i = 0; i < 16; i++) { local[i] = run; run += d_deg[base + i]; }
    sP[tid] = run;
    __syncthreads();
    for (int off = 1; off < 1024; off <<= 1) {
        int v = (tid >= off) ? sP[tid - off] : 0;
        __syncthreads();
        sP[tid] += v;
        __syncthreads();
    }
    int pre = (tid == 0) ? 0 : sP[tid - 1];
    #pragma unroll
    for (int i = 0; i < 16; i++) {
        int n = base + i;
        int rs = pre + local[i];
        d_rowstart[n] = rs;
        d_cursor[n] = rs + 1;   // slot 0 = self loop
        d_csrc[rs] = n;
    }
    if (tid == 1023) d_rowstart[NN] = sP[1023];
}
__global__ void k_scatter(const int* __restrict__ ei, int Eraw) {
    int i = blockIdx.x * blockDim.x + threadIdx.x;
    if (i >= Eraw) return;
    int s = __ldg(&ei[i]), d = __ldg(&ei[Eraw + i]);
    int pos = atomicAdd(&d_cursor[d], 1);
    d_csrc[pos] = s;
}

// ---------------- fused GAT layer 1 (H=2, C=64): warp per dst node ----------------
__global__ void k_gat1(const float* __restrict__ att, const float* __restrict__ bias1) {
    int w = (blockIdx.x * blockDim.x + threadIdx.x) >> 5;
    if (w >= NN) return;
    int lane = threadIdx.x & 31;
    float aA = att[lane], aB = att[lane + 32], aC = att[lane + 64], aD = att[lane + 96];
    const float* xr = d_xr1 + (size_t)w * 128;
    float r0 = xr[lane], r1 = xr[lane + 32], r2 = xr[lane + 64], r3 = xr[lane + 96];
    float acc0 = 0.f, acc1 = 0.f, acc2 = 0.f, acc3 = 0.f, s0 = 0.f, s1 = 0.f;
    int beg = d_rowstart[w], end = d_rowstart[w + 1];
    for (int i = beg; i < end; i++) {
        int s = d_csrc[i];
        const float* xl = d_xl1 + (size_t)s * 128;
        float v0 = xl[lane], v1 = xl[lane + 32], v2 = xl[lane + 64], v3 = xl[lane + 96];
        float t0 = v0 + r0; t0 = t0 > 0.f ? t0 : 0.2f * t0;
        float t1 = v1 + r1; t1 = t1 > 0.f ? t1 : 0.2f * t1;
        float t2 = v2 + r2; t2 = t2 > 0.f ? t2 : 0.2f * t2;
        float t3 = v3 + r3; t3 = t3 > 0.f ? t3 : 0.2f * t3;
        float p0 = t0 * aA + t1 * aB;
        float p1 = t2 * aC + t3 * aD;
        #pragma unroll
        for (int o = 16; o > 0; o >>= 1) {
            p0 += __shfl_xor_sync(0xFFFFFFFFu, p0, o);
            p1 += __shfl_xor_sync(0xFFFFFFFFu, p1, o);
        }
        float e0 = __expf(p0), e1 = __expf(p1);
        s0 += e0; s1 += e1;
        acc0 += e0 * v0; acc1 += e0 * v1; acc2 += e1 * v2; acc3 += e1 * v3;
    }
    float* o = d_h1 + (size_t)w * 128;
    float i0 = 1.f / s0, i1 = 1.f / s1;
    o[lane]      = bias1[lane]      + acc0 * i0;
    o[lane + 32] = bias1[lane + 32] + acc1 * i0;
    o[lane + 64] = bias1[lane + 64] + acc2 * i1;
    o[lane + 96] = bias1[lane + 96] + acc3 * i1;
}

// ---------------- fused GAT layer 2 (H=1, C=64): warp per dst node ----------------
__global__ void k_gat2(const float* __restrict__ att, const float* __restrict__ bias2) {
    int w = (blockIdx.x * blockDim.x + threadIdx.x) >> 5;
    if (w >= NN) return;
    int lane = threadIdx.x & 31;
    float aA = att[lane], aB = att[lane + 32];
    const float* xr = d_xr2 + (size_t)w * 64;
    float r0 = xr[lane], r1 = xr[lane + 32];
    float acc0 = 0.f, acc1 = 0.f, s0 = 0.f;
    int beg = d_rowstart[w], end = d_rowstart[w + 1];
    for (int i = beg; i < end; i++) {
        int s = d_csrc[i];
        const float* xl = d_xl2 + (size_t)s * 64;
        float v0 = xl[lane], v1 = xl[lane + 32];
        float t0 = v0 + r0; t0 = t0 > 0.f ? t0 : 0.2f * t0;
        float t1 = v1 + r1; t1 = t1 > 0.f ? t1 : 0.2f * t1;
        float p = t0 * aA + t1 * aB;
        #pragma unroll
        for (int o = 16; o > 0; o >>= 1) p += __shfl_xor_sync(0xFFFFFFFFu, p, o);
        float e = __expf(p);
        s0 += e;
        acc0 += e * v0; acc1 += e * v1;
    }
    float* o = d_h2 + (size_t)w * 64;
    float inv = 1.f / s0;
    o[lane]      = bias2[lane]      + acc0 * inv;
    o[lane + 32] = bias2[lane + 32] + acc1 * inv;
}

// ---------------- classifier: out = h2 @ Wc + bc ----------------
__global__ void k_cls(const float* __restrict__ Wc, const float* __restrict__ bc,
                      float* __restrict__ out) {
    int i = blockIdx.x * blockDim.x + threadIdx.x;
    if (i >= NN * 10) return;
    int n = i / 10, j = i % 10;
    const float* h = d_h2 + (size_t)n * 64;
    float acc = bc[j];
    #pragma unroll 16
    for (int k = 0; k < 64; k++) acc += h[k] * Wc[k * 10 + j];
    out[i] = acc;
}

// ---------------- launch ----------------
extern "C" void kernel_launch(void* const* d_in, const int* in_sizes, int n_in,
                              void* d_out, int out_size) {
    const float* x    = (const float*)d_in[0];
    const int*   ei   = (const int*)d_in[1];
    const float* c1w  = (const float*)d_in[2];
    const float* c1b  = (const float*)d_in[3];
    const float* c2w  = (const float*)d_in[4];
    const float* c2b  = (const float*)d_in[5];
    const float* Wl1  = (const float*)d_in[6];
    const float* bl1  = (const float*)d_in[7];
    const float* Wr1  = (const float*)d_in[8];
    const float* br1  = (const float*)d_in[9];
    const float* att1 = (const float*)d_in[10];
    const float* bias1= (const float*)d_in[11];
    const float* Wl2  = (const float*)d_in[12];
    const float* bl2  = (const float*)d_in[13];
    const float* Wr2  = (const float*)d_in[14];
    const float* br2  = (const float*)d_in[15];
    const float* att2 = (const float*)d_in[16];
    const float* bias2= (const float*)d_in[17];
    const float* Wc   = (const float*)d_in[18];
    const float* bc   = (const float*)d_in[19];
    float* out = (float*)d_out;

    int Eraw = in_sizes[1] / 2;
    int nodeBlocks = NN / 8;   // warp per node, 8 warps/block

    // CSR build (order preserved within the stream)
    k_deg_init<<<NN / 256, 256>>>();
    k_hist<<<(Eraw + 255) / 256, 256>>>(ei, Eraw);
    k_scan<<<1, 1024>>>();
    k_scatter<<<(Eraw + 255) / 256, 256>>>(ei, Eraw);

    // CNN feature extractor
    k_conv1<<<NN, 256>>>(x, c1w, c1b);
    k_conv2<<<NN, 196>>>(c2w, c2b);

    // GAT layer 1 (tf32 tensor-core GEMMs)
    k_gemm<0><<<dim3(2, NN / 128), 256>>>(Wl1, bl1, GIN, 128);
    k_gemm<1><<<dim3(2, NN / 128), 256>>>(Wr1, br1, GIN, 128);
    k_gat1<<<nodeBlocks, 256>>>(att1, bias1);

    // GAT layer 2 (ReLU on h1 fused into GEMM A-loads)
    k_gemm<2><<<dim3(1, NN / 128), 256>>>(Wl2, bl2, 128, 64);
    k_gemm<3><<<dim3(1, NN / 128), 256>>>(Wr2, br2, 128, 64);
    k_gat2<<<nodeBlocks, 256>>>(att2, bias2);

    // classifier
    k_cls<<<(NN * 10 + 255) / 256, 256>>>(Wc, bc, out);
}

// round 8
// speedup vs baseline: 4.3994x; 1.0071x over previous
#include <cuda_runtime.h>
#include <math.h>

#define NN 16384
#define GIN 1568
#define EMAX 540672   // 524288 + NN

// ---------------- scratch (static __device__, no allocation) ----------------
__device__ float d_c1buf[(size_t)NN * 16 * 14 * 14];
__device__ float d_h0[(size_t)NN * GIN];
__device__ float d_xl1[(size_t)NN * 128];
__device__ float d_xr1[(size_t)NN * 128];
__device__ float d_h1[(size_t)NN * 128];
__device__ float d_xl2[(size_t)NN * 64];
__device__ float d_xr2[(size_t)NN * 64];
__device__ float d_h2[(size_t)NN * 64];
__device__ int d_deg[NN];
__device__ int d_rowstart[NN + 1];
__device__ int d_cursor[NN];
__device__ int d_csrc[EMAX];

// ---------------- tf32 helpers ----------------
__device__ __forceinline__ unsigned f2tf32(float x) {
    unsigned u;
    asm("cvt.rna.tf32.f32 %0, %1;" : "=r"(u) : "f"(x));
    return u;
}
__device__ __forceinline__ void mma_tf32(float* d, const unsigned* a, const unsigned* b) {
    asm volatile(
        "mma.sync.aligned.m16n8k8.row.col.f32.tf32.tf32.f32 "
        "{%0,%1,%2,%3}, {%4,%5,%6,%7}, {%8,%9}, {%0,%1,%2,%3};\n"
        : "+f"(d[0]), "+f"(d[1]), "+f"(d[2]), "+f"(d[3])
        : "r"(a[0]), "r"(a[1]), "r"(a[2]), "r"(a[3]), "r"(b[0]), "r"(b[1]));
}

// ---------------- conv1 + relu + maxpool2 ----------------
__global__ void k_conv1(const float* __restrict__ x,
                        const float* __restrict__ w,
                        const float* __restrict__ b) {
    __shared__ float sIn[784];
    __shared__ float sW[144];
    __shared__ float sB[16];
    int n = blockIdx.x, tid = threadIdx.x;
    const float* xp = x + (size_t)n * 784;
    for (int i = tid; i < 784; i += 256) sIn[i] = xp[i];
    if (tid < 144) sW[tid] = w[tid];
    if (tid < 16) sB[tid] = b[tid];
    __syncthreads();
    for (int item = tid; item < 784; item += 256) {
        int ct = item / 196;
        int pos = item % 196;
        int py = pos / 14, px = pos % 14;
        int y0 = 2 * py - 1, x0 = 2 * px - 1;
        float patch[4][4];
        #pragma unroll
        for (int r = 0; r < 4; r++) {
            int iy = y0 + r;
            bool okY = (unsigned)iy < 28u;
            #pragma unroll
            for (int cc = 0; cc < 4; cc++) {
                int ix = x0 + cc;
                patch[r][cc] = (okY && (unsigned)ix < 28u) ? sIn[iy * 28 + ix] : 0.f;
            }
        }
        float acc[4][4];
        #pragma unroll
        for (int c8 = 0; c8 < 4; c8++) {
            float bb = sB[ct * 4 + c8];
            acc[c8][0] = acc[c8][1] = acc[c8][2] = acc[c8][3] = bb;
        }
        #pragma unroll
        for (int c8 = 0; c8 < 4; c8++) {
            const float* wp = &sW[(ct * 4 + c8) * 9];
            #pragma unroll
            for (int ky = 0; ky < 3; ky++) {
                #pragma unroll
                for (int kx = 0; kx < 3; kx++) {
                    float wv = wp[ky * 3 + kx];
                    acc[c8][0] += patch[ky][kx]         * wv;
                    acc[c8][1] += patch[ky][kx + 1]     * wv;
                    acc[c8][2] += patch[ky + 1][kx]     * wv;
                    acc[c8][3] += patch[ky + 1][kx + 1] * wv;
                }
            }
        }
        #pragma unroll
        for (int c8 = 0; c8 < 4; c8++) {
            float best = fmaxf(fmaxf(acc[c8][0], acc[c8][1]), fmaxf(acc[c8][2], acc[c8][3]));
            d_c1buf[(size_t)n * 3136 + (ct * 4 + c8) * 196 + pos] = fmaxf(best, 0.f);
        }
    }
}

// ---------------- conv2 via tf32 implicit GEMM ----------------
// Per image: C[196 pos][32 oc] = im2col(in)[196][144] @ W[144][32], then pool+bias+relu.
// Block = 1 image, 256 threads (8 warps). 13 m16-tiles; warp w handles tiles {w, w+8}.
#define AP 211   // As row pitch (16 x 211 words)
#define BP 40    // Bs row pitch (144 x 40 words)
__global__ void k_conv2(const float* __restrict__ w,
                        const float* __restrict__ b) {
    __shared__ float S[12272];          // 49088 bytes
    float* sIn = S;                      // [0 .. 3136)
    unsigned* As = (unsigned*)(S + 3136); // [16][AP] -> [3136 .. 6512)
    unsigned* Bs = (unsigned*)(S + 6512); // [144][BP] -> [6512 .. 12272)
    float* sC = S;                       // epilogue overlay: [196][33]

    int n = blockIdx.x, tid = threadIdx.x;
    const float* ip = d_c1buf + (size_t)n * 3136;
    for (int i = tid; i < 3136; i += 256) sIn[i] = ip[i];
    // stage B: w layout (32,16,3,3) -> flat oc*144 + k ; Bs[k][oc]
    for (int i = tid; i < 4608; i += 256) {
        int oc = i / 144, k = i - oc * 144;
        Bs[k * BP + oc] = f2tf32(__ldg(&w[i]));
    }
    __syncthreads();

    int warp = tid >> 5, lane = tid & 31;
    int g = lane >> 2, t = lane & 3;
    int kc = tid & 15;      // fixed k within chunk for staging
    int rbase = tid >> 4;   // 0..15

    float acc[2][4][4] = {};

    for (int chunk = 0; chunk < 9; chunk++) {
        // gather-stage A chunk (k = chunk*16 + kc), ci/ky/kx fixed per thread
        int k = chunk * 16 + kc;
        int ci = k / 9, rem = k - ci * 9;
        int ky = rem / 3, kx = rem - ky * 3;
        const float* inp = sIn + ci * 196;
        #pragma unroll
        for (int i = 0; i < 13; i++) {
            int pos = rbase + i * 16;   // 0..207
            float v = 0.f;
            if (pos < 196) {
                int y = pos / 14, x = pos - y * 14;
                int iy = y + ky - 1, ix = x + kx - 1;
                if ((unsigned)iy < 14u && (unsigned)ix < 14u)
                    v = inp[iy * 14 + ix];
            }
            As[kc * AP + pos] = f2tf32(v);
        }
        __syncthreads();

        #pragma unroll
        for (int kb = 0; kb < 2; kb++) {
            int kk = kb * 8;
            unsigned bfr[4][2];
            #pragma unroll
            for (int ni = 0; ni < 4; ni++) {
                bfr[ni][0] = Bs[(chunk * 16 + kk + t) * BP + ni * 8 + g];
                bfr[ni][1] = Bs[(chunk * 16 + kk + t + 4) * BP + ni * 8 + g];
            }
            #pragma unroll
            for (int mi = 0; mi < 2; mi++) {
                int mt = warp + mi * 8;
                if (mt < 13) {
                    int m = mt * 16;
                    unsigned a[4];
                    a[0] = As[(kk + t) * AP + m + g];
                    a[1] = As[(kk + t) * AP + m + g + 8];
                    a[2] = As[(kk + t + 4) * AP + m + g];
                    a[3] = As[(kk + t + 4) * AP + m + g + 8];
                    #pragma unroll
                    for (int ni = 0; ni < 4; ni++)
                        mma_tf32(acc[mi][ni], a, bfr[ni]);
                }
            }
        }
        __syncthreads();
    }

    // store pre-pool C to smem overlay (As/sIn dead after last sync)
    #pragma unroll
    for (int mi = 0; mi < 2; mi++) {
        int mt = warp + mi * 8;
        if (mt < 13) {
            int row0 = mt * 16 + g;
            #pragma unroll
            for (int ni = 0; ni < 4; ni++) {
                int col = ni * 8 + t * 2;
                if (row0 < 196) {
                    sC[row0 * 33 + col]     = acc[mi][ni][0];
                    sC[row0 * 33 + col + 1] = acc[mi][ni][1];
                }
                if (row0 + 8 < 196) {
                    sC[(row0 + 8) * 33 + col]     = acc[mi][ni][2];
                    sC[(row0 + 8) * 33 + col + 1] = acc[mi][ni][3];
                }
            }
        }
    }
    __syncthreads();

    // maxpool 2x2 + bias + relu -> d_h0 [n][oc*49 + p]
    for (int o = tid; o < 1568; o += 256) {
        int oc = o / 49, p = o - oc * 49;
        int py = p / 7, px = p - py * 7;
        int r0 = (2 * py) * 14 + 2 * px;
        float v = fmaxf(fmaxf(sC[r0 * 33 + oc],        sC[(r0 + 1) * 33 + oc]),
                        fmaxf(sC[(r0 + 14) * 33 + oc], sC[(r0 + 15) * 33 + oc]));
        v += __ldg(&b[oc]);
        d_h0[(size_t)n * 1568 + o] = fmaxf(v, 0.f);
    }
}

// ---------------- tf32 tensor-core GEMM: C = A(MxK)*B(KxNc) + bias ----------------
// Block tile 128x64, BK=16, 8 warps; warp = 32x32 (2 m16 x 4 n8 mma tiles).
// SEL: 0: A=d_h0,C=d_xl1 ; 1: A=d_h0,C=d_xr1 ; 2: A=relu(d_h1),C=d_xl2 ; 3: A=relu(d_h1),C=d_xr2
template <int SEL>
__global__ void k_gemm(const float* __restrict__ B,
                       const float* __restrict__ bias,
                       int K, int Nc) {
    const float* A = (SEL < 2) ? d_h0 : d_h1;
    float* C;
    if (SEL == 0) C = d_xl1;
    else if (SEL == 1) C = d_xr1;
    else if (SEL == 2) C = d_xl2;
    else C = d_xr2;

    __shared__ unsigned As[16][132];   // [k][m], padded
    __shared__ unsigned Bs[16][68];    // [k][n], padded

    int bm = blockIdx.y * 128, bn = blockIdx.x * 64;
    int tid = threadIdx.x;
    int warp = tid >> 5, lane = tid & 31;
    int g = lane >> 2, t = lane & 3;
    int mW = (warp >> 1) * 32, nW = (warp & 1) * 32;

    int arow = tid >> 1;            // 0..127
    int akc = (tid & 1) * 8;        // 0 or 8
    int bkr = tid >> 4;             // 0..15
    int bnc = (tid & 15) * 4;       // 0..60

    float acc[2][4][4] = {};

    for (int k0 = 0; k0 < K; k0 += 16) {
        const float* ap = &A[(size_t)(bm + arow) * K + k0 + akc];
        float4 av0 = *(const float4*)ap;
        float4 av1 = *(const float4*)(ap + 4);
        if (SEL >= 2) {
            av0.x = fmaxf(av0.x, 0.f); av0.y = fmaxf(av0.y, 0.f);
            av0.z = fmaxf(av0.z, 0.f); av0.w = fmaxf(av0.w, 0.f);
            av1.x = fmaxf(av1.x, 0.f); av1.y = fmaxf(av1.y, 0.f);
            av1.z = fmaxf(av1.z, 0.f); av1.w = fmaxf(av1.w, 0.f);
        }
        As[akc + 0][arow] = f2tf32(av0.x); As[akc + 1][arow] = f2tf32(av0.y);
        As[akc + 2][arow] = f2tf32(av0.z); As[akc + 3][arow] = f2tf32(av0.w);
        As[akc + 4][arow] = f2tf32(av1.x); As[akc + 5][arow] = f2tf32(av1.y);
        As[akc + 6][arow] = f2tf32(av1.z); As[akc + 7][arow] = f2tf32(av1.w);
        float4 bv = *(const float4*)&B[(size_t)(k0 + bkr) * Nc + bn + bnc];
        Bs[bkr][bnc + 0] = f2tf32(bv.x); Bs[bkr][bnc + 1] = f2tf32(bv.y);
        Bs[bkr][bnc + 2] = f2tf32(bv.z); Bs[bkr][bnc + 3] = f2tf32(bv.w);
        __syncthreads();

        #pragma unroll
        for (int kc = 0; kc < 2; kc++) {
            int kb = kc * 8;
            unsigned a[2][4], bfr[4][2];
            #pragma unroll
            for (int mi = 0; mi < 2; mi++) {
                int mrow = mW + mi * 16;
                a[mi][0] = As[kb + t][mrow + g];
                a[mi][1] = As[kb + t][mrow + g + 8];
                a[mi][2] = As[kb + t + 4][mrow + g];
                a[mi][3] = As[kb + t + 4][mrow + g + 8];
            }
            #pragma unroll
            for (int ni = 0; ni < 4; ni++) {
                bfr[ni][0] = Bs[kb + t][nW + ni * 8 + g];
                bfr[ni][1] = Bs[kb + t + 4][nW + ni * 8 + g];
            }
            #pragma unroll
            for (int mi = 0; mi < 2; mi++)
                #pragma unroll
                for (int ni = 0; ni < 4; ni++)
                    mma_tf32(acc[mi][ni], a[mi], bfr[ni]);
        }
        __syncthreads();
    }

    #pragma unroll
    for (int mi = 0; mi < 2; mi++) {
        int row0 = bm + mW + mi * 16 + g;
        #pragma unroll
        for (int ni = 0; ni < 4; ni++) {
            int col = bn + nW + ni * 8 + t * 2;
            float b0 = bias[col], b1 = bias[col + 1];
            C[(size_t)row0 * Nc + col]           = acc[mi][ni][0] + b0;
            C[(size_t)row0 * Nc + col + 1]       = acc[mi][ni][1] + b1;
            C[(size_t)(row0 + 8) * Nc + col]     = acc[mi][ni][2] + b0;
            C[(size_t)(row0 + 8) * Nc + col + 1] = acc[mi][ni][3] + b1;
        }
    }
}

// ---------------- CSR build ----------------
__global__ void k_deg_init() {
    int i = blockIdx.x * blockDim.x + threadIdx.x;
    if (i < NN) d_deg[i] = 1;   // self loop
}
__global__ void k_hist(const int* __restrict__ ei, int Eraw) {
    int i = blockIdx.x * blockDim.x + threadIdx.x;
    if (i < Eraw) atomicAdd(&d_deg[__ldg(&ei[Eraw + i])], 1);
}
__global__ void k_scan() {   // 1 block, 1024 threads, 16 elems each
    __shared__ int sP[1024];
    int tid = threadIdx.x;
    int base = tid * 16;
    int local[16];
    int run = 0;
    #pragma unroll
    for (int i = 0; i < 16; i++) { local[i] = run; run += d_deg[base + i]; }
    sP[tid] = run;
    __syncthreads();
    for (int off = 1; off < 1024; off <<= 1) {
        int v = (tid >= off) ? sP[tid - off] : 0;
        __syncthreads();
        sP[tid] += v;
        __syncthreads();
    }
    int pre = (tid == 0) ? 0 : sP[tid - 1];
    #pragma unroll
    for (int i = 0; i < 16; i++) {
        int n = base + i;
        int rs = pre + local[i];
        d_rowstart[n] = rs;
        d_cursor[n] = rs + 1;   // slot 0 = self loop
        d_csrc[rs] = n;
    }
    if (tid == 1023) d_rowstart[NN] = sP[1023];
}
__global__ void k_scatter(const int* __restrict__ ei, int Eraw) {
    int i = blockIdx.x * blockDim.x + threadIdx.x;
    if (i >= Eraw) return;
    int s = __ldg(&ei[i]), d = __ldg(&ei[Eraw + i]);
    int pos = atomicAdd(&d_cursor[d], 1);
    d_csrc[pos] = s;
}

// ---------------- fused GAT layer 1 (H=2, C=64): warp per dst node ----------------
__global__ void k_gat1(const float* __restrict__ att, const float* __restrict__ bias1) {
    int w = (blockIdx.x * blockDim.x + threadIdx.x) >> 5;
    if (w >= NN) return;
    int lane = threadIdx.x & 31;
    float aA = att[lane], aB = att[lane + 32], aC = att[lane + 64], aD = att[lane + 96];
    const float* xr = d_xr1 + (size_t)w * 128;
    float r0 = xr[lane], r1 = xr[lane + 32], r2 = xr[lane + 64], r3 = xr[lane + 96];
    float acc0 = 0.f, acc1 = 0.f, acc2 = 0.f, acc3 = 0.f, s0 = 0.f, s1 = 0.f;
    int beg = d_rowstart[w], end = d_rowstart[w + 1];
    for (int i = beg; i < end; i++) {
        int s = d_csrc[i];
        const float* xl = d_xl1 + (size_t)s * 128;
        float v0 = xl[lane], v1 = xl[lane + 32], v2 = xl[lane + 64], v3 = xl[lane + 96];
        float t0 = v0 + r0; t0 = t0 > 0.f ? t0 : 0.2f * t0;
        float t1 = v1 + r1; t1 = t1 > 0.f ? t1 : 0.2f * t1;
        float t2 = v2 + r2; t2 = t2 > 0.f ? t2 : 0.2f * t2;
        float t3 = v3 + r3; t3 = t3 > 0.f ? t3 : 0.2f * t3;
        float p0 = t0 * aA + t1 * aB;
        float p1 = t2 * aC + t3 * aD;
        #pragma unroll
        for (int o = 16; o > 0; o >>= 1) {
            p0 += __shfl_xor_sync(0xFFFFFFFFu, p0, o);
            p1 += __shfl_xor_sync(0xFFFFFFFFu, p1, o);
        }
        float e0 = __expf(p0), e1 = __expf(p1);
        s0 += e0; s1 += e1;
        acc0 += e0 * v0; acc1 += e0 * v1; acc2 += e1 * v2; acc3 += e1 * v3;
    }
    float* o = d_h1 + (size_t)w * 128;
    float i0 = 1.f / s0, i1 = 1.f / s1;
    o[lane]      = bias1[lane]      + acc0 * i0;
    o[lane + 32] = bias1[lane + 32] + acc1 * i0;
    o[lane + 64] = bias1[lane + 64] + acc2 * i1;
    o[lane + 96] = bias1[lane + 96] + acc3 * i1;
}

// ---------------- fused GAT layer 2 (H=1, C=64): warp per dst node ----------------
__global__ void k_gat2(const float* __restrict__ att, const float* __restrict__ bias2) {
    int w = (blockIdx.x * blockDim.x + threadIdx.x) >> 5;
    if (w >= NN) return;
    int lane = threadIdx.x & 31;
    float aA = att[lane], aB = att[lane + 32];
    const float* xr = d_xr2 + (size_t)w * 64;
    float r0 = xr[lane], r1 = xr[lane + 32];
    float acc0 = 0.f, acc1 = 0.f, s0 = 0.f;
    int beg = d_rowstart[w], end = d_rowstart[w + 1];
    for (int i = beg; i < end; i++) {
        int s = d_csrc[i];
        const float* xl = d_xl2 + (size_t)s * 64;
        float v0 = xl[lane], v1 = xl[lane + 32];
        float t0 = v0 + r0; t0 = t0 > 0.f ? t0 : 0.2f * t0;
        float t1 = v1 + r1; t1 = t1 > 0.f ? t1 : 0.2f * t1;
        float p = t0 * aA + t1 * aB;
        #pragma unroll
        for (int o = 16; o > 0; o >>= 1) p += __shfl_xor_sync(0xFFFFFFFFu, p, o);
        float e = __expf(p);
        s0 += e;
        acc0 += e * v0; acc1 += e * v1;
    }
    float* o = d_h2 + (size_t)w * 64;
    float inv = 1.f / s0;
    o[lane]      = bias2[lane]      + acc0 * inv;
    o[lane + 32] = bias2[lane + 32] + acc1 * inv;
}

// ---------------- classifier: out = h2 @ Wc + bc ----------------
__global__ void k_cls(const float* __restrict__ Wc, const float* __restrict__ bc,
                      float* __restrict__ out) {
    int i = blockIdx.x * blockDim.x + threadIdx.x;
    if (i >= NN * 10) return;
    int n = i / 10, j = i % 10;
    const float* h = d_h2 + (size_t)n * 64;
    float acc = bc[j];
    #pragma unroll 16
    for (int k = 0; k < 64; k++) acc += h[k] * Wc[k * 10 + j];
    out[i] = acc;
}

// ---------------- launch ----------------
extern "C" void kernel_launch(void* const* d_in, const int* in_sizes, int n_in,
                              void* d_out, int out_size) {
    const float* x    = (const float*)d_in[0];
    const int*   ei   = (const int*)d_in[1];
    const float* c1w  = (const float*)d_in[2];
    const float* c1b  = (const float*)d_in[3];
    const float* c2w  = (const float*)d_in[4];
    const float* c2b  = (const float*)d_in[5];
    const float* Wl1  = (const float*)d_in[6];
    const float* bl1  = (const float*)d_in[7];
    const float* Wr1  = (const float*)d_in[8];
    const float* br1  = (const float*)d_in[9];
    const float* att1 = (const float*)d_in[10];
    const float* bias1= (const float*)d_in[11];
    const float* Wl2  = (const float*)d_in[12];
    const float* bl2  = (const float*)d_in[13];
    const float* Wr2  = (const float*)d_in[14];
    const float* br2  = (const float*)d_in[15];
    const float* att2 = (const float*)d_in[16];
    const float* bias2= (const float*)d_in[17];
    const float* Wc   = (const float*)d_in[18];
    const float* bc   = (const float*)d_in[19];
    float* out = (float*)d_out;

    int Eraw = in_sizes[1] / 2;
    int nodeBlocks = NN / 8;   // warp per node, 8 warps/block

    // CSR build (order preserved within the stream)
    k_deg_init<<<NN / 256, 256>>>();
    k_hist<<<(Eraw + 255) / 256, 256>>>(ei, Eraw);
    k_scan<<<1, 1024>>>();
    k_scatter<<<(Eraw + 255) / 256, 256>>>(ei, Eraw);

    // CNN feature extractor
    k_conv1<<<NN, 256>>>(x, c1w, c1b);
    k_conv2<<<NN, 256>>>(c2w, c2b);

    // GAT layer 1 (tf32 tensor-core GEMMs)
    k_gemm<0><<<dim3(2, NN / 128), 256>>>(Wl1, bl1, GIN, 128);
    k_gemm<1><<<dim3(2, NN / 128), 256>>>(Wr1, br1, GIN, 128);
    k_gat1<<<nodeBlocks, 256>>>(att1, bias1);

    // GAT layer 2 (ReLU on h1 fused into GEMM A-loads)
    k_gemm<2><<<dim3(1, NN / 128), 256>>>(Wl2, bl2, 128, 64);
    k_gemm<3><<<dim3(1, NN / 128), 256>>>(Wr2, br2, 128, 64);
    k_gat2<<<nodeBlocks, 256>>>(att2, bias2);

    // classifier
    k_cls<<<(NN * 10 + 255) / 256, 256>>>(Wc, bc, out);
}

// round 9
// speedup vs baseline: 5.5779x; 1.2679x over previous
#include <cuda_runtime.h>
#include <math.h>

#define NN 16384
#define GIN 1568
#define EMAX 540672   // 524288 + NN

// ---------------- scratch (static __device__, no allocation) ----------------
__device__ float d_c1buf[(size_t)NN * 16 * 14 * 14];
__device__ float d_h0[(size_t)NN * GIN];
__device__ float d_xl1[(size_t)NN * 128];
__device__ float d_xr1[(size_t)NN * 128];
__device__ float d_h1[(size_t)NN * 128];
__device__ float d_xl2[(size_t)NN * 64];
__device__ float d_xr2[(size_t)NN * 64];
__device__ float d_h2[(size_t)NN * 64];
__device__ int d_deg[NN];
__device__ int d_rowstart[NN + 1];
__device__ int d_cursor[NN];
__device__ int d_csrc[EMAX];

// ---------------- helpers ----------------
__device__ __forceinline__ unsigned f2tf32(float x) {
    unsigned u;
    asm("cvt.rna.tf32.f32 %0, %1;" : "=r"(u) : "f"(x));
    return u;
}
__device__ __forceinline__ void mma_tf32(float* d, const unsigned* a, const unsigned* b) {
    asm volatile(
        "mma.sync.aligned.m16n8k8.row.col.f32.tf32.tf32.f32 "
        "{%0,%1,%2,%3}, {%4,%5,%6,%7}, {%8,%9}, {%0,%1,%2,%3};\n"
        : "+f"(d[0]), "+f"(d[1]), "+f"(d[2]), "+f"(d[3])
        : "r"(a[0]), "r"(a[1]), "r"(a[2]), "r"(a[3]), "r"(b[0]), "r"(b[1]));
}
__device__ __forceinline__ unsigned smaddr(const void* p) {
    unsigned a;
    asm("{ .reg .u64 t; cvta.to.shared.u64 t, %1; cvt.u32.u64 %0, t; }" : "=r"(a) : "l"(p));
    return a;
}
__device__ __forceinline__ void cp16(unsigned d, const void* s) {
    asm volatile("cp.async.cg.shared.global [%0], [%1], 16;" :: "r"(d), "l"(s));
}

// ---------------- conv1 + relu + maxpool2 ----------------
__global__ void k_conv1(const float* __restrict__ x,
                        const float* __restrict__ w,
                        const float* __restrict__ b) {
    __shared__ float sIn[784];
    __shared__ float sW[144];
    __shared__ float sB[16];
    int n = blockIdx.x, tid = threadIdx.x;
    const float* xp = x + (size_t)n * 784;
    for (int i = tid; i < 784; i += 256) sIn[i] = xp[i];
    if (tid < 144) sW[tid] = w[tid];
    if (tid < 16) sB[tid] = b[tid];
    __syncthreads();
    for (int item = tid; item < 784; item += 256) {
        int ct = item / 196;
        int pos = item % 196;
        int py = pos / 14, px = pos % 14;
        int y0 = 2 * py - 1, x0 = 2 * px - 1;
        float patch[4][4];
        #pragma unroll
        for (int r = 0; r < 4; r++) {
            int iy = y0 + r;
            bool okY = (unsigned)iy < 28u;
            #pragma unroll
            for (int cc = 0; cc < 4; cc++) {
                int ix = x0 + cc;
                patch[r][cc] = (okY && (unsigned)ix < 28u) ? sIn[iy * 28 + ix] : 0.f;
            }
        }
        float acc[4][4];
        #pragma unroll
        for (int c8 = 0; c8 < 4; c8++) {
            float bb = sB[ct * 4 + c8];
            acc[c8][0] = acc[c8][1] = acc[c8][2] = acc[c8][3] = bb;
        }
        #pragma unroll
        for (int c8 = 0; c8 < 4; c8++) {
            const float* wp = &sW[(ct * 4 + c8) * 9];
            #pragma unroll
            for (int ky = 0; ky < 3; ky++) {
                #pragma unroll
                for (int kx = 0; kx < 3; kx++) {
                    float wv = wp[ky * 3 + kx];
                    acc[c8][0] += patch[ky][kx]         * wv;
                    acc[c8][1] += patch[ky][kx + 1]     * wv;
                    acc[c8][2] += patch[ky + 1][kx]     * wv;
                    acc[c8][3] += patch[ky + 1][kx + 1] * wv;
                }
            }
        }
        #pragma unroll
        for (int c8 = 0; c8 < 4; c8++) {
            float best = fmaxf(fmaxf(acc[c8][0], acc[c8][1]), fmaxf(acc[c8][2], acc[c8][3]));
            d_c1buf[(size_t)n * 3136 + (ct * 4 + c8) * 196 + pos] = fmaxf(best, 0.f);
        }
    }
}

// ---------------- conv2 via tf32 implicit GEMM (linear im2col) ----------------
// pos grid is 14x16 padded (pos = y*16+x, M=224 = 14 m16-tiles).
// padded input sInP[ci][16x16] (1-px zero border):
//   A[pos][k=ci*9+ky*3+kx] = sInP[ci*256 + ky*16 + kx + pos]   (affine in pos!)
#define C2_SINP 0
#define C2_AS   4100
#define C2_AP   240
#define C2_BS   7940          // 4100 + 16*240
#define C2_BP   40
#define C2_WORDS 13700        // 7940 + 144*40
#define C2_BYTES (C2_WORDS * 4)
__global__ void k_conv2(const float* __restrict__ w,
                        const float* __restrict__ b) {
    extern __shared__ float S[];
    float* sInP = S + C2_SINP;            // 4100 floats (guarded)
    unsigned* As = (unsigned*)(S + C2_AS); // [16][240]
    unsigned* Bs = (unsigned*)(S + C2_BS); // [144][40]
    float* sC = S;                         // epilogue overlay [224][33] = 7392 < 7940

    int n = blockIdx.x, tid = threadIdx.x;
    const float* ip = d_c1buf + (size_t)n * 3136;

    for (int i = tid; i < 4100; i += 256) sInP[i] = 0.f;
    // stage B once: w layout (32,16,3,3) -> Bs[k][oc]
    for (int i = tid; i < 4608; i += 256) {
        int oc = i / 144, k = i - oc * 144;
        Bs[k * C2_BP + oc] = f2tf32(__ldg(&w[i]));
    }
    __syncthreads();
    for (int i = tid; i < 3136; i += 256) {
        int ci = i / 196, rem = i - ci * 196;
        int iy = rem / 14, ix = rem - iy * 14;
        sInP[ci * 256 + (iy + 1) * 16 + ix + 1] = ip[i];
    }
    __syncthreads();

    int warp = tid >> 5, lane = tid & 31;
    int g = lane >> 2, t = lane & 3;
    int kc = tid >> 4;       // 0..15: k within chunk
    int rbase = tid & 15;    // 0..15: pos offset

    float acc[2][4][4] = {};

    for (int chunk = 0; chunk < 9; chunk++) {
        // linear im2col staging: 14 shifted contiguous copies
        int k = chunk * 16 + kc;
        int ci = k / 9, rem = k - ci * 9;
        int ky = rem / 3, kx = rem - ky * 3;
        const float* src = sInP + ci * 256 + ky * 16 + kx;
        unsigned* dst = As + kc * C2_AP;
        #pragma unroll
        for (int i = 0; i < 14; i++) {
            int pos = rbase + i * 16;
            dst[pos] = f2tf32(src[pos]);
        }
        __syncthreads();

        #pragma unroll
        for (int kb = 0; kb < 2; kb++) {
            int kk = kb * 8;
            unsigned bfr[4][2];
            #pragma unroll
            for (int ni = 0; ni < 4; ni++) {
                bfr[ni][0] = Bs[(chunk * 16 + kk + t) * C2_BP + ni * 8 + g];
                bfr[ni][1] = Bs[(chunk * 16 + kk + t + 4) * C2_BP + ni * 8 + g];
            }
            #pragma unroll
            for (int mi = 0; mi < 2; mi++) {
                int mt = warp + mi * 8;
                if (mt < 14) {
                    int m = mt * 16;
                    unsigned a[4];
                    a[0] = As[(kk + t) * C2_AP + m + g];
                    a[1] = As[(kk + t) * C2_AP + m + g + 8];
                    a[2] = As[(kk + t + 4) * C2_AP + m + g];
                    a[3] = As[(kk + t + 4) * C2_AP + m + g + 8];
                    #pragma unroll
                    for (int ni = 0; ni < 4; ni++)
                        mma_tf32(acc[mi][ni], a, bfr[ni]);
                }
            }
        }
        __syncthreads();
    }

    // store pre-pool C (overlay; sInP/As dead)
    #pragma unroll
    for (int mi = 0; mi < 2; mi++) {
        int mt = warp + mi * 8;
        if (mt < 14) {
            int row0 = mt * 16 + g;
            #pragma unroll
            for (int ni = 0; ni < 4; ni++) {
                int col = ni * 8 + t * 2;
                sC[row0 * 33 + col]           = acc[mi][ni][0];
                sC[row0 * 33 + col + 1]       = acc[mi][ni][1];
                sC[(row0 + 8) * 33 + col]     = acc[mi][ni][2];
                sC[(row0 + 8) * 33 + col + 1] = acc[mi][ni][3];
            }
        }
    }
    __syncthreads();

    // maxpool 2x2 + bias + relu -> d_h0
    for (int o = tid; o < 1568; o += 256) {
        int oc = o / 49, p = o - oc * 49;
        int py = p / 7, px = p - py * 7;
        int pos00 = py * 32 + px * 2;   // (2py)*16 + 2px
        float v = fmaxf(fmaxf(sC[pos00 * 33 + oc],        sC[(pos00 + 1) * 33 + oc]),
                        fmaxf(sC[(pos00 + 16) * 33 + oc], sC[(pos00 + 17) * 33 + oc]));
        v += __ldg(&b[oc]);
        d_h0[(size_t)n * 1568 + o] = fmaxf(v, 0.f);
    }
}

// ---------------- tf32 GEMM, cp.async double-buffered ----------------
// Block tile 128x64, BK=16, 8 warps; warp = 32x32 (2 m16 x 4 n8 mma tiles).
// Raw fp32 staged via cp.async; ReLU (SEL>=2) + tf32 cvt at fragment load.
// SEL: 0: A=d_h0,C=d_xl1 ; 1: A=d_h0,C=d_xr1 ; 2: A=relu(d_h1),C=d_xl2 ; 3: A=relu(d_h1),C=d_xr2
template <int SEL>
__global__ void k_gemm(const float* __restrict__ Bm,
                       const float* __restrict__ bias,
                       int K, int Nc) {
    const float* A = (SEL < 2) ? d_h0 : d_h1;
    float* C;
    if (SEL == 0) C = d_xl1;
    else if (SEL == 1) C = d_xr1;
    else if (SEL == 2) C = d_xl2;
    else C = d_xr2;

    __shared__ float As[2][128][20];   // [m][k], pitch 20 -> conflict-free frags
    __shared__ float Bs[2][16][72];    // [k][n], pitch 72 -> conflict-free frags

    int bm = blockIdx.y * 128, bn = blockIdx.x * 64;
    int tid = threadIdx.x;
    int warp = tid >> 5, lane = tid & 31;
    int g = lane >> 2, t = lane & 3;
    int mW = (warp >> 1) * 32, nW = (warp & 1) * 32;

    int arow = tid >> 1, akq = (tid & 1) * 8;   // A: 2x16B per thread
    int brow = tid >> 4, bq = (tid & 15) * 4;   // B: 1x16B per thread

    const float* aSrc = A + (size_t)(bm + arow) * K + akq;
    const float* bSrc = Bm + (size_t)brow * Nc + bn + bq;

    float acc[2][4][4] = {};
    int niter = K >> 4;

    cp16(smaddr(&As[0][arow][akq]),     aSrc);
    cp16(smaddr(&As[0][arow][akq + 4]), aSrc + 4);
    cp16(smaddr(&Bs[0][brow][bq]),      bSrc);
    asm volatile("cp.async.commit_group;");

    for (int it = 0; it < niter; it++) {
        int buf = it & 1;
        if (it + 1 < niter) {
            int k0 = (it + 1) << 4;
            cp16(smaddr(&As[buf ^ 1][arow][akq]),     aSrc + k0);
            cp16(smaddr(&As[buf ^ 1][arow][akq + 4]), aSrc + k0 + 4);
            cp16(smaddr(&Bs[buf ^ 1][brow][bq]),      bSrc + (size_t)k0 * Nc);
            asm volatile("cp.async.commit_group;");
            asm volatile("cp.async.wait_group 1;");
        } else {
            asm volatile("cp.async.wait_group 0;");
        }
        __syncthreads();

        #pragma unroll
        for (int kb = 0; kb < 2; kb++) {
            int kk = kb * 8;
            unsigned a[2][4], bfr[4][2];
            #pragma unroll
            for (int mi = 0; mi < 2; mi++) {
                int mrow = mW + mi * 16;
                float x0 = As[buf][mrow + g][kk + t];
                float x1 = As[buf][mrow + g + 8][kk + t];
                float x2 = As[buf][mrow + g][kk + t + 4];
                float x3 = As[buf][mrow + g + 8][kk + t + 4];
                if (SEL >= 2) {
                    x0 = fmaxf(x0, 0.f); x1 = fmaxf(x1, 0.f);
                    x2 = fmaxf(x2, 0.f); x3 = fmaxf(x3, 0.f);
                }
                a[mi][0] = f2tf32(x0); a[mi][1] = f2tf32(x1);
                a[mi][2] = f2tf32(x2); a[mi][3] = f2tf32(x3);
            }
            #pragma unroll
            for (int ni = 0; ni < 4; ni++) {
                bfr[ni][0] = f2tf32(Bs[buf][kk + t][nW + ni * 8 + g]);
                bfr[ni][1] = f2tf32(Bs[buf][kk + t + 4][nW + ni * 8 + g]);
            }
            #pragma unroll
            for (int mi = 0; mi < 2; mi++)
                #pragma unroll
                for (int ni = 0; ni < 4; ni++)
                    mma_tf32(acc[mi][ni], a[mi], bfr[ni]);
        }
        __syncthreads();
    }

    #pragma unroll
    for (int mi = 0; mi < 2; mi++) {
        int row0 = bm + mW + mi * 16 + g;
        #pragma unroll
        for (int ni = 0; ni < 4; ni++) {
            int col = bn + nW + ni * 8 + t * 2;
            float b0 = bias[col], b1 = bias[col + 1];
            C[(size_t)row0 * Nc + col]           = acc[mi][ni][0] + b0;
            C[(size_t)row0 * Nc + col + 1]       = acc[mi][ni][1] + b1;
            C[(size_t)(row0 + 8) * Nc + col]     = acc[mi][ni][2] + b0;
            C[(size_t)(row0 + 8) * Nc + col + 1] = acc[mi][ni][3] + b1;
        }
    }
}

// ---------------- CSR build ----------------
__global__ void k_deg_init() {
    int i = blockIdx.x * blockDim.x + threadIdx.x;
    if (i < NN) d_deg[i] = 1;   // self loop
}
__global__ void k_hist(const int* __restrict__ ei, int Eraw) {
    int i = blockIdx.x * blockDim.x + threadIdx.x;
    if (i < Eraw) atomicAdd(&d_deg[__ldg(&ei[Eraw + i])], 1);
}
__global__ void k_scan() {   // 1 block, 1024 threads, 16 elems each
    __shared__ int sP[1024];
    int tid = threadIdx.x;
    int base = tid * 16;
    int local[16];
    int run = 0;
    #pragma unroll
    for (int i = 0; i < 16; i++) { local[i] = run; run += d_deg[base + i]; }
    sP[tid] = run;
    __syncthreads();
    for (int off = 1; off < 1024; off <<= 1) {
        int v = (tid >= off) ? sP[tid - off] : 0;
        __syncthreads();
        sP[tid] += v;
        __syncthreads();
    }
    int pre = (tid == 0) ? 0 : sP[tid - 1];
    #pragma unroll
    for (int i = 0; i < 16; i++) {
        int n = base + i;
        int rs = pre + local[i];
        d_rowstart[n] = rs;
        d_cursor[n] = rs + 1;   // slot 0 = self loop
        d_csrc[rs] = n;
    }
    if (tid == 1023) d_rowstart[NN] = sP[1023];
}
__global__ void k_scatter(const int* __restrict__ ei, int Eraw) {
    int i = blockIdx.x * blockDim.x + threadIdx.x;
    if (i >= Eraw) return;
    int s = __ldg(&ei[i]), d = __ldg(&ei[Eraw + i]);
    int pos = atomicAdd(&d_cursor[d], 1);
    d_csrc[pos] = s;
}

// ---------------- fused GAT layer 1 (H=2, C=64): warp per dst node ----------------
__global__ void k_gat1(const float* __restrict__ att, const float* __restrict__ bias1) {
    int w = (blockIdx.x * blockDim.x + threadIdx.x) >> 5;
    if (w >= NN) return;
    int lane = threadIdx.x & 31;
    float aA = att[lane], aB = att[lane + 32], aC = att[lane + 64], aD = att[lane + 96];
    const float* xr = d_xr1 + (size_t)w * 128;
    float r0 = xr[lane], r1 = xr[lane + 32], r2 = xr[lane + 64], r3 = xr[lane + 96];
    float acc0 = 0.f, acc1 = 0.f, acc2 = 0.f, acc3 = 0.f, s0 = 0.f, s1 = 0.f;
    int beg = d_rowstart[w], end = d_rowstart[w + 1];
    for (int i = beg; i < end; i++) {
        int s = d_csrc[i];
        const float* xl = d_xl1 + (size_t)s * 128;
        float v0 = xl[lane], v1 = xl[lane + 32], v2 = xl[lane + 64], v3 = xl[lane + 96];
        float t0 = v0 + r0; t0 = t0 > 0.f ? t0 : 0.2f * t0;
        float t1 = v1 + r1; t1 = t1 > 0.f ? t1 : 0.2f * t1;
        float t2 = v2 + r2; t2 = t2 > 0.f ? t2 : 0.2f * t2;
        float t3 = v3 + r3; t3 = t3 > 0.f ? t3 : 0.2f * t3;
        float p0 = t0 * aA + t1 * aB;
        float p1 = t2 * aC + t3 * aD;
        #pragma unroll
        for (int o = 16; o > 0; o >>= 1) {
            p0 += __shfl_xor_sync(0xFFFFFFFFu, p0, o);
            p1 += __shfl_xor_sync(0xFFFFFFFFu, p1, o);
        }
        float e0 = __expf(p0), e1 = __expf(p1);
        s0 += e0; s1 += e1;
        acc0 += e0 * v0; acc1 += e0 * v1; acc2 += e1 * v2; acc3 += e1 * v3;
    }
    float* o = d_h1 + (size_t)w * 128;
    float i0 = 1.f / s0, i1 = 1.f / s1;
    o[lane]      = bias1[lane]      + acc0 * i0;
    o[lane + 32] = bias1[lane + 32] + acc1 * i0;
    o[lane + 64] = bias1[lane + 64] + acc2 * i1;
    o[lane + 96] = bias1[lane + 96] + acc3 * i1;
}

// ---------------- fused GAT layer 2 (H=1, C=64): warp per dst node ----------------
__global__ void k_gat2(const float* __restrict__ att, const float* __restrict__ bias2) {
    int w = (blockIdx.x * blockDim.x + threadIdx.x) >> 5;
    if (w >= NN) return;
    int lane = threadIdx.x & 31;
    float aA = att[lane], aB = att[lane + 32];
    const float* xr = d_xr2 + (size_t)w * 64;
    float r0 = xr[lane], r1 = xr[lane + 32];
    float acc0 = 0.f, acc1 = 0.f, s0 = 0.f;
    int beg = d_rowstart[w], end = d_rowstart[w + 1];
    for (int i = beg; i < end; i++) {
        int s = d_csrc[i];
        const float* xl = d_xl2 + (size_t)s * 64;
        float v0 = xl[lane], v1 = xl[lane + 32];
        float t0 = v0 + r0; t0 = t0 > 0.f ? t0 : 0.2f * t0;
        float t1 = v1 + r1; t1 = t1 > 0.f ? t1 : 0.2f * t1;
        float p = t0 * aA + t1 * aB;
        #pragma unroll
        for (int o = 16; o > 0; o >>= 1) p += __shfl_xor_sync(0xFFFFFFFFu, p, o);
        float e = __expf(p);
        s0 += e;
        acc0 += e * v0; acc1 += e * v1;
    }
    float* o = d_h2 + (size_t)w * 64;
    float inv = 1.f / s0;
    o[lane]      = bias2[lane]      + acc0 * inv;
    o[lane + 32] = bias2[lane + 32] + acc1 * inv;
}

// ---------------- classifier: out = h2 @ Wc + bc ----------------
__global__ void k_cls(const float* __restrict__ Wc, const float* __restrict__ bc,
                      float* __restrict__ out) {
    int i = blockIdx.x * blockDim.x + threadIdx.x;
    if (i >= NN * 10) return;
    int n = i / 10, j = i % 10;
    const float* h = d_h2 + (size_t)n * 64;
    float acc = bc[j];
    #pragma unroll 16
    for (int k = 0; k < 64; k++) acc += h[k] * Wc[k * 10 + j];
    out[i] = acc;
}

// ---------------- launch ----------------
extern "C" void kernel_launch(void* const* d_in, const int* in_sizes, int n_in,
                              void* d_out, int out_size) {
    const float* x    = (const float*)d_in[0];
    const int*   ei   = (const int*)d_in[1];
    const float* c1w  = (const float*)d_in[2];
    const float* c1b  = (const float*)d_in[3];
    const float* c2w  = (const float*)d_in[4];
    const float* c2b  = (const float*)d_in[5];
    const float* Wl1  = (const float*)d_in[6];
    const float* bl1  = (const float*)d_in[7];
    const float* Wr1  = (const float*)d_in[8];
    const float* br1  = (const float*)d_in[9];
    const float* att1 = (const float*)d_in[10];
    const float* bias1= (const float*)d_in[11];
    const float* Wl2  = (const float*)d_in[12];
    const float* bl2  = (const float*)d_in[13];
    const float* Wr2  = (const float*)d_in[14];
    const float* br2  = (const float*)d_in[15];
    const float* att2 = (const float*)d_in[16];
    const float* bias2= (const float*)d_in[17];
    const float* Wc   = (const float*)d_in[18];
    const float* bc   = (const float*)d_in[19];
    float* out = (float*)d_out;

    int Eraw = in_sizes[1] / 2;
    int nodeBlocks = NN / 8;   // warp per node, 8 warps/block

    // conv2 needs >48KB dynamic smem (idempotent; not a stream op)
    cudaFuncSetAttribute(k_conv2, cudaFuncAttributeMaxDynamicSharedMemorySize, C2_BYTES);

    // CSR build (order preserved within the stream)
    k_deg_init<<<NN / 256, 256>>>();
    k_hist<<<(Eraw + 255) / 256, 256>>>(ei, Eraw);
    k_scan<<<1, 1024>>>();
    k_scatter<<<(Eraw + 255) / 256, 256>>>(ei, Eraw);

    // CNN feature extractor
    k_conv1<<<NN, 256>>>(x, c1w, c1b);
    k_conv2<<<NN, 256, C2_BYTES>>>(c2w, c2b);

    // GAT layer 1 (tf32 tensor-core GEMMs, cp.async pipelined)
    k_gemm<0><<<dim3(2, NN / 128), 256>>>(Wl1, bl1, GIN, 128);
    k_gemm<1><<<dim3(2, NN / 128), 256>>>(Wr1, br1, GIN, 128);
    k_gat1<<<nodeBlocks, 256>>>(att1, bias1);

    // GAT layer 2 (ReLU on h1 fused into GEMM fragment loads)
    k_gemm<2><<<dim3(1, NN / 128), 256>>>(Wl2, bl2, 128, 64);
    k_gemm<3><<<dim3(1, NN / 128), 256>>>(Wr2, br2, 128, 64);
    k_gat2<<<nodeBlocks, 256>>>(att2, bias2);

    // classifier
    k_cls<<<(NN * 10 + 255) / 256, 256>>>(Wc, bc, out);
}

// round 10
// speedup vs baseline: 6.4979x; 1.1649x over previous
#include <cuda_runtime.h>
#include <math.h>

#define NN 16384
#define GIN 1568
#define EMAX 540672   // 524288 + NN

// ---------------- scratch (static __device__, no allocation) ----------------
__device__ float d_c1buf[(size_t)NN * 16 * 14 * 14];
__device__ float d_h0[(size_t)NN * GIN];
__device__ float d_xl1[(size_t)NN * 128];
__device__ float d_xr1[(size_t)NN * 128];
__device__ float d_h1[(size_t)NN * 128];
__device__ float d_xl2[(size_t)NN * 64];
__device__ float d_xr2[(size_t)NN * 64];
__device__ float d_h2[(size_t)NN * 64];
__device__ int d_deg[NN];
__device__ int d_rowstart[NN + 1];
__device__ int d_cursor[NN];
__device__ int d_csrc[EMAX];

// ---------------- helpers ----------------
__device__ __forceinline__ unsigned f2tf32(float x) {
    unsigned u;
    asm("cvt.rna.tf32.f32 %0, %1;" : "=r"(u) : "f"(x));
    return u;
}
__device__ __forceinline__ void mma_tf32(float* d, const unsigned* a, const unsigned* b) {
    asm volatile(
        "mma.sync.aligned.m16n8k8.row.col.f32.tf32.tf32.f32 "
        "{%0,%1,%2,%3}, {%4,%5,%6,%7}, {%8,%9}, {%0,%1,%2,%3};\n"
        : "+f"(d[0]), "+f"(d[1]), "+f"(d[2]), "+f"(d[3])
        : "r"(a[0]), "r"(a[1]), "r"(a[2]), "r"(a[3]), "r"(b[0]), "r"(b[1]));
}
__device__ __forceinline__ unsigned smaddr(const void* p) {
    unsigned a;
    asm("{ .reg .u64 t; cvta.to.shared.u64 t, %1; cvt.u32.u64 %0, t; }" : "=r"(a) : "l"(p));
    return a;
}
__device__ __forceinline__ void cp16(unsigned d, const void* s) {
    asm volatile("cp.async.cg.shared.global [%0], [%1], 16;" :: "r"(d), "l"(s));
}

// ---------------- conv1 + relu + maxpool2 ----------------
__global__ void k_conv1(const float* __restrict__ x,
                        const float* __restrict__ w,
                        const float* __restrict__ b) {
    __shared__ float sIn[784];
    __shared__ float sW[144];
    __shared__ float sB[16];
    int n = blockIdx.x, tid = threadIdx.x;
    const float* xp = x + (size_t)n * 784;
    for (int i = tid; i < 784; i += 256) sIn[i] = xp[i];
    if (tid < 144) sW[tid] = w[tid];
    if (tid < 16) sB[tid] = b[tid];
    __syncthreads();
    for (int item = tid; item < 784; item += 256) {
        int ct = item / 196;
        int pos = item % 196;
        int py = pos / 14, px = pos % 14;
        int y0 = 2 * py - 1, x0 = 2 * px - 1;
        float patch[4][4];
        #pragma unroll
        for (int r = 0; r < 4; r++) {
            int iy = y0 + r;
            bool okY = (unsigned)iy < 28u;
            #pragma unroll
            for (int cc = 0; cc < 4; cc++) {
                int ix = x0 + cc;
                patch[r][cc] = (okY && (unsigned)ix < 28u) ? sIn[iy * 28 + ix] : 0.f;
            }
        }
        float acc[4][4];
        #pragma unroll
        for (int c8 = 0; c8 < 4; c8++) {
            float bb = sB[ct * 4 + c8];
            acc[c8][0] = acc[c8][1] = acc[c8][2] = acc[c8][3] = bb;
        }
        #pragma unroll
        for (int c8 = 0; c8 < 4; c8++) {
            const float* wp = &sW[(ct * 4 + c8) * 9];
            #pragma unroll
            for (int ky = 0; ky < 3; ky++) {
                #pragma unroll
                for (int kx = 0; kx < 3; kx++) {
                    float wv = wp[ky * 3 + kx];
                    acc[c8][0] += patch[ky][kx]         * wv;
                    acc[c8][1] += patch[ky][kx + 1]     * wv;
                    acc[c8][2] += patch[ky + 1][kx]     * wv;
                    acc[c8][3] += patch[ky + 1][kx + 1] * wv;
                }
            }
        }
        #pragma unroll
        for (int c8 = 0; c8 < 4; c8++) {
            float best = fmaxf(fmaxf(acc[c8][0], acc[c8][1]), fmaxf(acc[c8][2], acc[c8][3]));
            d_c1buf[(size_t)n * 3136 + (ct * 4 + c8) * 196 + pos] = fmaxf(best, 0.f);
        }
    }
}

// ---------------- conv2 via tf32 implicit GEMM, zero-staging ----------------
// pos grid 14x16 padded (pos=y*16+x, M=224). A[pos][k] = sInP[off[k] + pos],
// off[k] = ci*256 + ky*16 + kx  (affine in pos) -> A-fragments read DIRECTLY
// from the padded input; no staging buffer, no mainloop syncthreads.
#define C2_BP 40
__global__ void k_conv2(const float* __restrict__ w,
                        const float* __restrict__ b) {
    __shared__ float S[10004];              // 40016 B
    float* sInP = S;                         // [0..4100)  16ci x 256 (+guard)
    unsigned* Bs = (unsigned*)(S + 4100);    // [4100..9860)  144 x 40
    int* offTab = (int*)(S + 9860);          // [9860..10004)
    float* sC = S;                           // epilogue overlay [224][33]=7392

    int n = blockIdx.x, tid = threadIdx.x;
    const float* ip = d_c1buf + (size_t)n * 3136;

    for (int i = tid; i < 4100; i += 256) sInP[i] = 0.f;
    for (int i = tid; i < 4608; i += 256) {          // w (32,16,3,3): Bs[k][oc]
        int oc = i / 144, k = i - oc * 144;
        Bs[k * C2_BP + oc] = f2tf32(__ldg(&w[i]));
    }
    if (tid < 144) {
        int ci = tid / 9, rem = tid - ci * 9;
        offTab[tid] = ci * 256 + (rem / 3) * 16 + (rem % 3);
    }
    __syncthreads();
    for (int i = tid; i < 3136; i += 256) {
        int ci = i / 196, rem = i - ci * 196;
        int iy = rem / 14, ix = rem - iy * 14;
        sInP[ci * 256 + (iy + 1) * 16 + ix + 1] = ip[i];
    }
    __syncthreads();

    int warp = tid >> 5, lane = tid & 31;
    int g = lane >> 2, t = lane & 3;

    float acc[2][4][4] = {};

    for (int chunk = 0; chunk < 9; chunk++) {
        int c16 = chunk * 16;
        int o0 = offTab[c16 + t];        // kb=0: k = c16 + t
        int o1 = offTab[c16 + t + 4];    //        k = c16 + t + 4
        int o2 = offTab[c16 + t + 8];    // kb=1
        int o3 = offTab[c16 + t + 12];
        #pragma unroll
        for (int kb = 0; kb < 2; kb++) {
            int oA = kb ? o2 : o0, oB = kb ? o3 : o1;
            int krow = c16 + kb * 8;
            unsigned bfr[4][2];
            #pragma unroll
            for (int ni = 0; ni < 4; ni++) {
                bfr[ni][0] = Bs[(krow + t) * C2_BP + ni * 8 + g];
                bfr[ni][1] = Bs[(krow + t + 4) * C2_BP + ni * 8 + g];
            }
            #pragma unroll
            for (int mi = 0; mi < 2; mi++) {
                int mt = warp + mi * 8;
                if (mt < 14) {
                    int m = mt * 16;
                    unsigned a[4];
                    a[0] = f2tf32(sInP[oA + m + g]);
                    a[1] = f2tf32(sInP[oA + m + g + 8]);
                    a[2] = f2tf32(sInP[oB + m + g]);
                    a[3] = f2tf32(sInP[oB + m + g + 8]);
                    #pragma unroll
                    for (int ni = 0; ni < 4; ni++)
                        mma_tf32(acc[mi][ni], a, bfr[ni]);
                }
            }
        }
    }
    __syncthreads();   // sInP/Bs dead; reuse as sC

    #pragma unroll
    for (int mi = 0; mi < 2; mi++) {
        int mt = warp + mi * 8;
        if (mt < 14) {
            int row0 = mt * 16 + g;
            #pragma unroll
            for (int ni = 0; ni < 4; ni++) {
                int col = ni * 8 + t * 2;
                sC[row0 * 33 + col]           = acc[mi][ni][0];
                sC[row0 * 33 + col + 1]       = acc[mi][ni][1];
                sC[(row0 + 8) * 33 + col]     = acc[mi][ni][2];
                sC[(row0 + 8) * 33 + col + 1] = acc[mi][ni][3];
            }
        }
    }
    __syncthreads();

    for (int o = tid; o < 1568; o += 256) {
        int oc = o / 49, p = o - oc * 49;
        int py = p / 7, px = p - py * 7;
        int pos00 = py * 32 + px * 2;
        float v = fmaxf(fmaxf(sC[pos00 * 33 + oc],        sC[(pos00 + 1) * 33 + oc]),
                        fmaxf(sC[(pos00 + 16) * 33 + oc], sC[(pos00 + 17) * 33 + oc]));
        v += __ldg(&b[oc]);
        d_h0[(size_t)n * 1568 + o] = fmaxf(v, 0.f);
    }
}

// ---------------- tf32 GEMM, cp.async double-buffered ----------------
template <int SEL>
__global__ void k_gemm(const float* __restrict__ Bm,
                       const float* __restrict__ bias,
                       int K, int Nc) {
    const float* A = (SEL < 2) ? d_h0 : d_h1;
    float* C;
    if (SEL == 0) C = d_xl1;
    else if (SEL == 1) C = d_xr1;
    else if (SEL == 2) C = d_xl2;
    else C = d_xr2;

    __shared__ float As[2][128][20];
    __shared__ float Bs[2][16][72];

    int bm = blockIdx.y * 128, bn = blockIdx.x * 64;
    int tid = threadIdx.x;
    int warp = tid >> 5, lane = tid & 31;
    int g = lane >> 2, t = lane & 3;
    int mW = (warp >> 1) * 32, nW = (warp & 1) * 32;

    int arow = tid >> 1, akq = (tid & 1) * 8;
    int brow = tid >> 4, bq = (tid & 15) * 4;

    const float* aSrc = A + (size_t)(bm + arow) * K + akq;
    const float* bSrc = Bm + (size_t)brow * Nc + bn + bq;

    float acc[2][4][4] = {};
    int niter = K >> 4;

    cp16(smaddr(&As[0][arow][akq]),     aSrc);
    cp16(smaddr(&As[0][arow][akq + 4]), aSrc + 4);
    cp16(smaddr(&Bs[0][brow][bq]),      bSrc);
    asm volatile("cp.async.commit_group;");

    for (int it = 0; it < niter; it++) {
        int buf = it & 1;
        if (it + 1 < niter) {
            int k0 = (it + 1) << 4;
            cp16(smaddr(&As[buf ^ 1][arow][akq]),     aSrc + k0);
            cp16(smaddr(&As[buf ^ 1][arow][akq + 4]), aSrc + k0 + 4);
            cp16(smaddr(&Bs[buf ^ 1][brow][bq]),      bSrc + (size_t)k0 * Nc);
            asm volatile("cp.async.commit_group;");
            asm volatile("cp.async.wait_group 1;");
        } else {
            asm volatile("cp.async.wait_group 0;");
        }
        __syncthreads();

        #pragma unroll
        for (int kb = 0; kb < 2; kb++) {
            int kk = kb * 8;
            unsigned a[2][4], bfr[4][2];
            #pragma unroll
            for (int mi = 0; mi < 2; mi++) {
                int mrow = mW + mi * 16;
                float x0 = As[buf][mrow + g][kk + t];
                float x1 = As[buf][mrow + g + 8][kk + t];
                float x2 = As[buf][mrow + g][kk + t + 4];
                float x3 = As[buf][mrow + g + 8][kk + t + 4];
                if (SEL >= 2) {
                    x0 = fmaxf(x0, 0.f); x1 = fmaxf(x1, 0.f);
                    x2 = fmaxf(x2, 0.f); x3 = fmaxf(x3, 0.f);
                }
                a[mi][0] = f2tf32(x0); a[mi][1] = f2tf32(x1);
                a[mi][2] = f2tf32(x2); a[mi][3] = f2tf32(x3);
            }
            #pragma unroll
            for (int ni = 0; ni < 4; ni++) {
                bfr[ni][0] = f2tf32(Bs[buf][kk + t][nW + ni * 8 + g]);
                bfr[ni][1] = f2tf32(Bs[buf][kk + t + 4][nW + ni * 8 + g]);
            }
            #pragma unroll
            for (int mi = 0; mi < 2; mi++)
                #pragma unroll
                for (int ni = 0; ni < 4; ni++)
                    mma_tf32(acc[mi][ni], a[mi], bfr[ni]);
        }
        __syncthreads();
    }

    #pragma unroll
    for (int mi = 0; mi < 2; mi++) {
        int row0 = bm + mW + mi * 16 + g;
        #pragma unroll
        for (int ni = 0; ni < 4; ni++) {
            int col = bn + nW + ni * 8 + t * 2;
            float b0 = bias[col], b1 = bias[col + 1];
            C[(size_t)row0 * Nc + col]           = acc[mi][ni][0] + b0;
            C[(size_t)row0 * Nc + col + 1]       = acc[mi][ni][1] + b1;
            C[(size_t)(row0 + 8) * Nc + col]     = acc[mi][ni][2] + b0;
            C[(size_t)(row0 + 8) * Nc + col + 1] = acc[mi][ni][3] + b1;
        }
    }
}

// ---------------- CSR build ----------------
__global__ void k_deg_init() {
    int i = blockIdx.x * blockDim.x + threadIdx.x;
    if (i < NN) d_deg[i] = 1;
}
__global__ void k_hist(const int* __restrict__ ei, int Eraw) {
    int i = blockIdx.x * blockDim.x + threadIdx.x;
    if (i < Eraw) atomicAdd(&d_deg[__ldg(&ei[Eraw + i])], 1);
}
__global__ void k_scan() {
    __shared__ int sP[1024];
    int tid = threadIdx.x;
    int base = tid * 16;
    int local[16];
    int run = 0;
    #pragma unroll
    for (int i = 0; i < 16; i++) { local[i] = run; run += d_deg[base + i]; }
    sP[tid] = run;
    __syncthreads();
    for (int off = 1; off < 1024; off <<= 1) {
        int v = (tid >= off) ? sP[tid - off] : 0;
        __syncthreads();
        sP[tid] += v;
        __syncthreads();
    }
    int pre = (tid == 0) ? 0 : sP[tid - 1];
    #pragma unroll
    for (int i = 0; i < 16; i++) {
        int n = base + i;
        int rs = pre + local[i];
        d_rowstart[n] = rs;
        d_cursor[n] = rs + 1;
        d_csrc[rs] = n;
    }
    if (tid == 1023) d_rowstart[NN] = sP[1023];
}
__global__ void k_scatter(const int* __restrict__ ei, int Eraw) {
    int i = blockIdx.x * blockDim.x + threadIdx.x;
    if (i >= Eraw) return;
    int s = __ldg(&ei[i]), d = __ldg(&ei[Eraw + i]);
    int pos = atomicAdd(&d_cursor[d], 1);
    d_csrc[pos] = s;
}

// ---------------- fused GAT layer 1 (H=2, C=64) ----------------
__global__ void k_gat1(const float* __restrict__ att, const float* __restrict__ bias1) {
    int w = (blockIdx.x * blockDim.x + threadIdx.x) >> 5;
    if (w >= NN) return;
    int lane = threadIdx.x & 31;
    float aA = att[lane], aB = att[lane + 32], aC = att[lane + 64], aD = att[lane + 96];
    const float* xr = d_xr1 + (size_t)w * 128;
    float r0 = xr[lane], r1 = xr[lane + 32], r2 = xr[lane + 64], r3 = xr[lane + 96];
    float acc0 = 0.f, acc1 = 0.f, acc2 = 0.f, acc3 = 0.f, s0 = 0.f, s1 = 0.f;
    int beg = d_rowstart[w], end = d_rowstart[w + 1];
    for (int i = beg; i < end; i++) {
        int s = d_csrc[i];
        const float* xl = d_xl1 + (size_t)s * 128;
        float v0 = xl[lane], v1 = xl[lane + 32], v2 = xl[lane + 64], v3 = xl[lane + 96];
        float t0 = v0 + r0; t0 = t0 > 0.f ? t0 : 0.2f * t0;
        float t1 = v1 + r1; t1 = t1 > 0.f ? t1 : 0.2f * t1;
        float t2 = v2 + r2; t2 = t2 > 0.f ? t2 : 0.2f * t2;
        float t3 = v3 + r3; t3 = t3 > 0.f ? t3 : 0.2f * t3;
        float p0 = t0 * aA + t1 * aB;
        float p1 = t2 * aC + t3 * aD;
        #pragma unroll
        for (int o = 16; o > 0; o >>= 1) {
            p0 += __shfl_xor_sync(0xFFFFFFFFu, p0, o);
            p1 += __shfl_xor_sync(0xFFFFFFFFu, p1, o);
        }
        float e0 = __expf(p0), e1 = __expf(p1);
        s0 += e0; s1 += e1;
        acc0 += e0 * v0; acc1 += e0 * v1; acc2 += e1 * v2; acc3 += e1 * v3;
    }
    float* o = d_h1 + (size_t)w * 128;
    float i0 = 1.f / s0, i1 = 1.f / s1;
    o[lane]      = bias1[lane]      + acc0 * i0;
    o[lane + 32] = bias1[lane + 32] + acc1 * i0;
    o[lane + 64] = bias1[lane + 64] + acc2 * i1;
    o[lane + 96] = bias1[lane + 96] + acc3 * i1;
}

// ---------------- fused GAT layer 2 (H=1, C=64) ----------------
__global__ void k_gat2(const float* __restrict__ att, const float* __restrict__ bias2) {
    int w = (blockIdx.x * blockDim.x + threadIdx.x) >> 5;
    if (w >= NN) return;
    int lane = threadIdx.x & 31;
    float aA = att[lane], aB = att[lane + 32];
    const float* xr = d_xr2 + (size_t)w * 64;
    float r0 = xr[lane], r1 = xr[lane + 32];
    float acc0 = 0.f, acc1 = 0.f, s0 = 0.f;
    int beg = d_rowstart[w], end = d_rowstart[w + 1];
    for (int i = beg; i < end; i++) {
        int s = d_csrc[i];
        const float* xl = d_xl2 + (size_t)s * 64;
        float v0 = xl[lane], v1 = xl[lane + 32];
        float t0 = v0 + r0; t0 = t0 > 0.f ? t0 : 0.2f * t0;
        float t1 = v1 + r1; t1 = t1 > 0.f ? t1 : 0.2f * t1;
        float p = t0 * aA + t1 * aB;
        #pragma unroll
        for (int o = 16; o > 0; o >>= 1) p += __shfl_xor_sync(0xFFFFFFFFu, p, o);
        float e = __expf(p);
        s0 += e;
        acc0 += e * v0; acc1 += e * v1;
    }
    float* o = d_h2 + (size_t)w * 64;
    float inv = 1.f / s0;
    o[lane]      = bias2[lane]      + acc0 * inv;
    o[lane + 32] = bias2[lane + 32] + acc1 * inv;
}

// ---------------- classifier ----------------
__global__ void k_cls(const float* __restrict__ Wc, const float* __restrict__ bc,
                      float* __restrict__ out) {
    int i = blockIdx.x * blockDim.x + threadIdx.x;
    if (i >= NN * 10) return;
    int n = i / 10, j = i % 10;
    const float* h = d_h2 + (size_t)n * 64;
    float acc = bc[j];
    #pragma unroll 16
    for (int k = 0; k < 64; k++) acc += h[k] * Wc[k * 10 + j];
    out[i] = acc;
}

// ---------------- launch ----------------
extern "C" void kernel_launch(void* const* d_in, const int* in_sizes, int n_in,
                              void* d_out, int out_size) {
    const float* x    = (const float*)d_in[0];
    const int*   ei   = (const int*)d_in[1];
    const float* c1w  = (const float*)d_in[2];
    const float* c1b  = (const float*)d_in[3];
    const float* c2w  = (const float*)d_in[4];
    const float* c2b  = (const float*)d_in[5];
    const float* Wl1  = (const float*)d_in[6];
    const float* bl1  = (const float*)d_in[7];
    const float* Wr1  = (const float*)d_in[8];
    const float* br1  = (const float*)d_in[9];
    const float* att1 = (const float*)d_in[10];
    const float* bias1= (const float*)d_in[11];
    const float* Wl2  = (const float*)d_in[12];
    const float* bl2  = (const float*)d_in[13];
    const float* Wr2  = (const float*)d_in[14];
    const float* br2  = (const float*)d_in[15];
    const float* att2 = (const float*)d_in[16];
    const float* bias2= (const float*)d_in[17];
    const float* Wc   = (const float*)d_in[18];
    const float* bc   = (const float*)d_in[19];
    float* out = (float*)d_out;

    int Eraw = in_sizes[1] / 2;
    int nodeBlocks = NN / 8;

    // Interleaved order (dependency-safe) so conv2 lands in the ncu-captured
    // launch slot: deg(1), conv1(2), hist(3), conv2(4), scan(5), scatter(6).
    k_deg_init<<<NN / 256, 256>>>();
    k_conv1<<<NN, 256>>>(x, c1w, c1b);
    k_hist<<<(Eraw + 255) / 256, 256>>>(ei, Eraw);
    k_conv2<<<NN, 256>>>(c2w, c2b);
    k_scan<<<1, 1024>>>();
    k_scatter<<<(Eraw + 255) / 256, 256>>>(ei, Eraw);

    // GAT layer 1
    k_gemm<0><<<dim3(2, NN / 128), 256>>>(Wl1, bl1, GIN, 128);
    k_gemm<1><<<dim3(2, NN / 128), 256>>>(Wr1, br1, GIN, 128);
    k_gat1<<<nodeBlocks, 256>>>(att1, bias1);

    // GAT layer 2
    k_gemm<2><<<dim3(1, NN / 128), 256>>>(Wl2, bl2, 128, 64);
    k_gemm<3><<<dim3(1, NN / 128), 256>>>(Wr2, br2, 128, 64);
    k_gat2<<<nodeBlocks, 256>>>(att2, bias2);

    // classifier
    k_cls<<<(NN * 10 + 255) / 256, 256>>>(Wc, bc, out);
}

// round 11
// speedup vs baseline: 8.3078x; 1.2785x over previous
#include <cuda_runtime.h>
#include <math.h>

#define NN 16384
#define GIN 1568
#define EMAX 540672   // 524288 + NN

// ---------------- scratch (static __device__, no allocation) ----------------
__device__ float d_h0[(size_t)NN * GIN];
__device__ float d_xl1[(size_t)NN * 128];
__device__ float d_xr1[(size_t)NN * 128];
__device__ float d_h1[(size_t)NN * 128];
__device__ float d_xl2[(size_t)NN * 64];
__device__ float d_xr2[(size_t)NN * 64];
__device__ float d_h2[(size_t)NN * 64];
__device__ int d_deg[NN];
__device__ int d_rowstart[NN + 1];
__device__ int d_cursor[NN];
__device__ int d_csrc[EMAX];

// ---------------- helpers ----------------
__device__ __forceinline__ unsigned f2tf32(float x) {
    unsigned u;
    asm("cvt.rna.tf32.f32 %0, %1;" : "=r"(u) : "f"(x));
    return u;
}
__device__ __forceinline__ void mma_tf32(float* d, const unsigned* a, const unsigned* b) {
    asm volatile(
        "mma.sync.aligned.m16n8k8.row.col.f32.tf32.tf32.f32 "
        "{%0,%1,%2,%3}, {%4,%5,%6,%7}, {%8,%9}, {%0,%1,%2,%3};\n"
        : "+f"(d[0]), "+f"(d[1]), "+f"(d[2]), "+f"(d[3])
        : "r"(a[0]), "r"(a[1]), "r"(a[2]), "r"(a[3]), "r"(b[0]), "r"(b[1]));
}
__device__ __forceinline__ unsigned smaddr(const void* p) {
    unsigned a;
    asm("{ .reg .u64 t; cvta.to.shared.u64 t, %1; cvt.u32.u64 %0, t; }" : "=r"(a) : "l"(p));
    return a;
}
__device__ __forceinline__ void cp16(unsigned d, const void* s) {
    asm volatile("cp.async.cg.shared.global [%0], [%1], 16;" :: "r"(d), "l"(s));
}

// ---------------- fused conv1+pool+conv2+pool (tf32 implicit GEMM) ----------------
// Block = 1 image. conv1 output (pooled 16x14x14) never leaves smem.
// conv2: pos grid 14x16 padded (pos=y*16+x, M=224), A[pos][k] = sInP[off[k]+pos]
// with sInP pre-converted to tf32 bits; Bs[k][oc] tf32.
#define C2_BP 40
__global__ void k_convf(const float* __restrict__ x,
                        const float* __restrict__ w1,
                        const float* __restrict__ b1,
                        const float* __restrict__ w2,
                        const float* __restrict__ b2) {
    __shared__ float S[10948];                 // 43792 B static
    float*    sImg  = S;                        // [0..784)
    float*    sW1   = S + 784;                  // [784..928)
    float*    sB1   = S + 928;                  // [928..944)
    unsigned* sInP  = (unsigned*)(S + 944);     // [944..5044)   16ci x 256, tf32 bits
    unsigned* Bs    = (unsigned*)(S + 5044);    // [5044..10804) 144 x 40
    int*      offT  = (int*)(S + 10804);        // [10804..10948)
    float*    sC    = S;                        // epilogue overlay [224][33]=7392

    int n = blockIdx.x, tid = threadIdx.x;

    // ---- stage: image, conv1 weights, conv2 weights (tf32), offsets, zero pad ----
    for (int i = tid; i < 4100; i += 256) sInP[i] = 0u;
    const float* xp = x + (size_t)n * 784;
    for (int i = tid; i < 784; i += 256) sImg[i] = xp[i];
    if (tid < 144) sW1[tid] = w1[tid];
    if (tid < 16) sB1[tid] = b1[tid];
    for (int i = tid; i < 4608; i += 256) {     // w2 (32,16,3,3): Bs[k][oc]
        int oc = i / 144, k = i - oc * 144;
        Bs[k * C2_BP + oc] = f2tf32(__ldg(&w2[i]));
    }
    if (tid < 144) {
        int ci = tid / 9, rem = tid - ci * 9;
        offT[tid] = ci * 256 + (rem / 3) * 16 + (rem % 3);
    }
    __syncthreads();

    // ---- conv1 + relu + maxpool -> sInP (padded, tf32 bits) ----
    for (int item = tid; item < 784; item += 256) {
        int ct = item / 196;           // 4-channel tile
        int pos = item % 196;
        int py = pos / 14, px = pos % 14;
        int y0 = 2 * py - 1, x0 = 2 * px - 1;
        float patch[4][4];
        #pragma unroll
        for (int r = 0; r < 4; r++) {
            int iy = y0 + r;
            bool okY = (unsigned)iy < 28u;
            #pragma unroll
            for (int cc = 0; cc < 4; cc++) {
                int ix = x0 + cc;
                patch[r][cc] = (okY && (unsigned)ix < 28u) ? sImg[iy * 28 + ix] : 0.f;
            }
        }
        #pragma unroll
        for (int c8 = 0; c8 < 4; c8++) {
            int c = ct * 4 + c8;
            float bb = sB1[c];
            float a0 = bb, a1 = bb, a2 = bb, a3 = bb;
            const float* wp = &sW1[c * 9];
            #pragma unroll
            for (int ky = 0; ky < 3; ky++) {
                #pragma unroll
                for (int kx = 0; kx < 3; kx++) {
                    float wv = wp[ky * 3 + kx];
                    a0 += patch[ky][kx]         * wv;
                    a1 += patch[ky][kx + 1]     * wv;
                    a2 += patch[ky + 1][kx]     * wv;
                    a3 += patch[ky + 1][kx + 1] * wv;
                }
            }
            float best = fmaxf(fmaxf(a0, a1), fmaxf(a2, a3));
            sInP[c * 256 + (py + 1) * 16 + px + 1] = f2tf32(fmaxf(best, 0.f));
        }
    }
    __syncthreads();

    // ---- conv2 mainloop: zero-staging implicit GEMM, no cvt, no syncs ----
    int warp = tid >> 5, lane = tid & 31;
    int g = lane >> 2, t = lane & 3;

    float acc[2][4][4] = {};

    #pragma unroll
    for (int chunk = 0; chunk < 9; chunk++) {
        int c16 = chunk * 16;
        int o0 = offT[c16 + t];
        int o1 = offT[c16 + t + 4];
        int o2 = offT[c16 + t + 8];
        int o3 = offT[c16 + t + 12];
        #pragma unroll
        for (int kb = 0; kb < 2; kb++) {
            int oA = kb ? o2 : o0, oB = kb ? o3 : o1;
            int krow = c16 + kb * 8;
            unsigned bfr[4][2];
            #pragma unroll
            for (int ni = 0; ni < 4; ni++) {
                bfr[ni][0] = Bs[(krow + t) * C2_BP + ni * 8 + g];
                bfr[ni][1] = Bs[(krow + t + 4) * C2_BP + ni * 8 + g];
            }
            #pragma unroll
            for (int mi = 0; mi < 2; mi++) {
                int mt = warp + mi * 8;
                if (mt < 14) {
                    int m = mt * 16;
                    unsigned a[4];
                    a[0] = sInP[oA + m + g];
                    a[1] = sInP[oA + m + g + 8];
                    a[2] = sInP[oB + m + g];
                    a[3] = sInP[oB + m + g + 8];
                    #pragma unroll
                    for (int ni = 0; ni < 4; ni++)
                        mma_tf32(acc[mi][ni], a, bfr[ni]);
                }
            }
        }
    }
    __syncthreads();   // all smem dead; reuse as sC

    #pragma unroll
    for (int mi = 0; mi < 2; mi++) {
        int mt = warp + mi * 8;
        if (mt < 14) {
            int row0 = mt * 16 + g;
            #pragma unroll
            for (int ni = 0; ni < 4; ni++) {
                int col = ni * 8 + t * 2;
                sC[row0 * 33 + col]           = acc[mi][ni][0];
                sC[row0 * 33 + col + 1]       = acc[mi][ni][1];
                sC[(row0 + 8) * 33 + col]     = acc[mi][ni][2];
                sC[(row0 + 8) * 33 + col + 1] = acc[mi][ni][3];
            }
        }
    }
    __syncthreads();

    for (int o = tid; o < 1568; o += 256) {
        int oc = o / 49, p = o - oc * 49;
        int py = p / 7, px = p - py * 7;
        int pos00 = py * 32 + px * 2;
        float v = fmaxf(fmaxf(sC[pos00 * 33 + oc],        sC[(pos00 + 1) * 33 + oc]),
                        fmaxf(sC[(pos00 + 16) * 33 + oc], sC[(pos00 + 17) * 33 + oc]));
        v += __ldg(&b2[oc]);
        d_h0[(size_t)n * 1568 + o] = fmaxf(v, 0.f);
    }
}

// ---------------- dual tf32 GEMM: stages A once, computes l AND r outputs ----------------
// SEL 0: A=d_h0 (K=1568, Nc=128) -> d_xl1/d_xr1 ; SEL 1: A=relu(d_h1) (K=128, Nc=64) -> d_xl2/d_xr2
template <int SEL>
__global__ void k_gemmd(const float* __restrict__ Bl, const float* __restrict__ biasl,
                        const float* __restrict__ Br, const float* __restrict__ biasr,
                        int K, int Nc) {
    const float* A = (SEL == 0) ? d_h0 : d_h1;
    float* Cl = (SEL == 0) ? d_xl1 : d_xl2;
    float* Cr = (SEL == 0) ? d_xr1 : d_xr2;

    __shared__ float As[2][128][20];
    __shared__ float Bsl[2][16][72];
    __shared__ float Bsr[2][16][72];

    int bm = blockIdx.y * 128, bn = blockIdx.x * 64;
    int tid = threadIdx.x;
    int warp = tid >> 5, lane = tid & 31;
    int g = lane >> 2, t = lane & 3;
    int mW = (warp >> 1) * 32, nW = (warp & 1) * 32;

    int arow = tid >> 1, akq = (tid & 1) * 8;
    int brow = tid >> 4, bq = (tid & 15) * 4;

    const float* aSrc  = A + (size_t)(bm + arow) * K + akq;
    const float* blSrc = Bl + (size_t)brow * Nc + bn + bq;
    const float* brSrc = Br + (size_t)brow * Nc + bn + bq;

    float accL[2][4][4] = {}, accR[2][4][4] = {};
    int niter = K >> 4;

    cp16(smaddr(&As[0][arow][akq]),     aSrc);
    cp16(smaddr(&As[0][arow][akq + 4]), aSrc + 4);
    cp16(smaddr(&Bsl[0][brow][bq]),     blSrc);
    cp16(smaddr(&Bsr[0][brow][bq]),     brSrc);
    asm volatile("cp.async.commit_group;");

    for (int it = 0; it < niter; it++) {
        int buf = it & 1;
        if (it + 1 < niter) {
            int k0 = (it + 1) << 4;
            cp16(smaddr(&As[buf ^ 1][arow][akq]),     aSrc + k0);
            cp16(smaddr(&As[buf ^ 1][arow][akq + 4]), aSrc + k0 + 4);
            cp16(smaddr(&Bsl[buf ^ 1][brow][bq]),     blSrc + (size_t)k0 * Nc);
            cp16(smaddr(&Bsr[buf ^ 1][brow][bq]),     brSrc + (size_t)k0 * Nc);
            asm volatile("cp.async.commit_group;");
            asm volatile("cp.async.wait_group 1;");
        } else {
            asm volatile("cp.async.wait_group 0;");
        }
        __syncthreads();

        #pragma unroll
        for (int kb = 0; kb < 2; kb++) {
            int kk = kb * 8;
            unsigned a[2][4], bL[4][2], bR[4][2];
            #pragma unroll
            for (int mi = 0; mi < 2; mi++) {
                int mrow = mW + mi * 16;
                float x0 = As[buf][mrow + g][kk + t];
                float x1 = As[buf][mrow + g + 8][kk + t];
                float x2 = As[buf][mrow + g][kk + t + 4];
                float x3 = As[buf][mrow + g + 8][kk + t + 4];
                if (SEL == 1) {
                    x0 = fmaxf(x0, 0.f); x1 = fmaxf(x1, 0.f);
                    x2 = fmaxf(x2, 0.f); x3 = fmaxf(x3, 0.f);
                }
                a[mi][0] = f2tf32(x0); a[mi][1] = f2tf32(x1);
                a[mi][2] = f2tf32(x2); a[mi][3] = f2tf32(x3);
            }
            #pragma unroll
            for (int ni = 0; ni < 4; ni++) {
                bL[ni][0] = f2tf32(Bsl[buf][kk + t][nW + ni * 8 + g]);
                bL[ni][1] = f2tf32(Bsl[buf][kk + t + 4][nW + ni * 8 + g]);
                bR[ni][0] = f2tf32(Bsr[buf][kk + t][nW + ni * 8 + g]);
                bR[ni][1] = f2tf32(Bsr[buf][kk + t + 4][nW + ni * 8 + g]);
            }
            #pragma unroll
            for (int mi = 0; mi < 2; mi++)
                #pragma unroll
                for (int ni = 0; ni < 4; ni++) {
                    mma_tf32(accL[mi][ni], a[mi], bL[ni]);
                    mma_tf32(accR[mi][ni], a[mi], bR[ni]);
                }
        }
        __syncthreads();
    }

    #pragma unroll
    for (int mi = 0; mi < 2; mi++) {
        int row0 = bm + mW + mi * 16 + g;
        #pragma unroll
        for (int ni = 0; ni < 4; ni++) {
            int col = bn + nW + ni * 8 + t * 2;
            float bl0 = biasl[col], bl1 = biasl[col + 1];
            float br0 = biasr[col], br1 = biasr[col + 1];
            Cl[(size_t)row0 * Nc + col]           = accL[mi][ni][0] + bl0;
            Cl[(size_t)row0 * Nc + col + 1]       = accL[mi][ni][1] + bl1;
            Cl[(size_t)(row0 + 8) * Nc + col]     = accL[mi][ni][2] + bl0;
            Cl[(size_t)(row0 + 8) * Nc + col + 1] = accL[mi][ni][3] + bl1;
            Cr[(size_t)row0 * Nc + col]           = accR[mi][ni][0] + br0;
            Cr[(size_t)row0 * Nc + col + 1]       = accR[mi][ni][1] + br1;
            Cr[(size_t)(row0 + 8) * Nc + col]     = accR[mi][ni][2] + br0;
            Cr[(size_t)(row0 + 8) * Nc + col + 1] = accR[mi][ni][3] + br1;
        }
    }
}

// ---------------- CSR build ----------------
__global__ void k_deg_init() {
    int i = blockIdx.x * blockDim.x + threadIdx.x;
    if (i < NN) d_deg[i] = 1;
}
__global__ void k_hist(const int* __restrict__ ei, int Eraw) {
    int i = blockIdx.x * blockDim.x + threadIdx.x;
    if (i < Eraw) atomicAdd(&d_deg[__ldg(&ei[Eraw + i])], 1);
}
__global__ void k_scan() {
    __shared__ int sP[1024];
    int tid = threadIdx.x;
    int base = tid * 16;
    int local[16];
    int run = 0;
    #pragma unroll
    for (int i = 0; i < 16; i++) { local[i] = run; run += d_deg[base + i]; }
    sP[tid] = run;
    __syncthreads();
    for (int off = 1; off < 1024; off <<= 1) {
        int v = (tid >= off) ? sP[tid - off] : 0;
        __syncthreads();
        sP[tid] += v;
        __syncthreads();
    }
    int pre = (tid == 0) ? 0 : sP[tid - 1];
    #pragma unroll
    for (int i = 0; i < 16; i++) {
        int n = base + i;
        int rs = pre + local[i];
        d_rowstart[n] = rs;
        d_cursor[n] = rs + 1;
        d_csrc[rs] = n;
    }
    if (tid == 1023) d_rowstart[NN] = sP[1023];
}
__global__ void k_scatter(const int* __restrict__ ei, int Eraw) {
    int i = blockIdx.x * blockDim.x + threadIdx.x;
    if (i >= Eraw) return;
    int s = __ldg(&ei[i]), d = __ldg(&ei[Eraw + i]);
    int pos = atomicAdd(&d_cursor[d], 1);
    d_csrc[pos] = s;
}

// ---------------- fused GAT layer 1 (H=2, C=64) ----------------
__global__ void k_gat1(const float* __restrict__ att, const float* __restrict__ bias1) {
    int w = (blockIdx.x * blockDim.x + threadIdx.x) >> 5;
    if (w >= NN) return;
    int lane = threadIdx.x & 31;
    float aA = att[lane], aB = att[lane + 32], aC = att[lane + 64], aD = att[lane + 96];
    const float* xr = d_xr1 + (size_t)w * 128;
    float r0 = xr[lane], r1 = xr[lane + 32], r2 = xr[lane + 64], r3 = xr[lane + 96];
    float acc0 = 0.f, acc1 = 0.f, acc2 = 0.f, acc3 = 0.f, s0 = 0.f, s1 = 0.f;
    int beg = d_rowstart[w], end = d_rowstart[w + 1];
    for (int i = beg; i < end; i++) {
        int s = d_csrc[i];
        const float* xl = d_xl1 + (size_t)s * 128;
        float v0 = xl[lane], v1 = xl[lane + 32], v2 = xl[lane + 64], v3 = xl[lane + 96];
        float t0 = v0 + r0; t0 = t0 > 0.f ? t0 : 0.2f * t0;
        float t1 = v1 + r1; t1 = t1 > 0.f ? t1 : 0.2f * t1;
        float t2 = v2 + r2; t2 = t2 > 0.f ? t2 : 0.2f * t2;
        float t3 = v3 + r3; t3 = t3 > 0.f ? t3 : 0.2f * t3;
        float p0 = t0 * aA + t1 * aB;
        float p1 = t2 * aC + t3 * aD;
        #pragma unroll
        for (int o = 16; o > 0; o >>= 1) {
            p0 += __shfl_xor_sync(0xFFFFFFFFu, p0, o);
            p1 += __shfl_xor_sync(0xFFFFFFFFu, p1, o);
        }
        float e0 = __expf(p0), e1 = __expf(p1);
        s0 += e0; s1 += e1;
        acc0 += e0 * v0; acc1 += e0 * v1; acc2 += e1 * v2; acc3 += e1 * v3;
    }
    float* o = d_h1 + (size_t)w * 128;
    float i0 = 1.f / s0, i1 = 1.f / s1;
    o[lane]      = bias1[lane]      + acc0 * i0;
    o[lane + 32] = bias1[lane + 32] + acc1 * i0;
    o[lane + 64] = bias1[lane + 64] + acc2 * i1;
    o[lane + 96] = bias1[lane + 96] + acc3 * i1;
}

// ---------------- fused GAT layer 2 (H=1, C=64) ----------------
__global__ void k_gat2(const float* __restrict__ att, const float* __restrict__ bias2) {
    int w = (blockIdx.x * blockDim.x + threadIdx.x) >> 5;
    if (w >= NN) return;
    int lane = threadIdx.x & 31;
    float aA = att[lane], aB = att[lane + 32];
    const float* xr = d_xr2 + (size_t)w * 64;
    float r0 = xr[lane], r1 = xr[lane + 32];
    float acc0 = 0.f, acc1 = 0.f, s0 = 0.f;
    int beg = d_rowstart[w], end = d_rowstart[w + 1];
    for (int i = beg; i < end; i++) {
        int s = d_csrc[i];
        const float* xl = d_xl2 + (size_t)s * 64;
        float v0 = xl[lane], v1 = xl[lane + 32];
        float t0 = v0 + r0; t0 = t0 > 0.f ? t0 : 0.2f * t0;
        float t1 = v1 + r1; t1 = t1 > 0.f ? t1 : 0.2f * t1;
        float p = t0 * aA + t1 * aB;
        #pragma unroll
        for (int o = 16; o > 0; o >>= 1) p += __shfl_xor_sync(0xFFFFFFFFu, p, o);
        float e = __expf(p);
        s0 += e;
        acc0 += e * v0; acc1 += e * v1;
    }
    float* o = d_h2 + (size_t)w * 64;
    float inv = 1.f / s0;
    o[lane]      = bias2[lane]      + acc0 * inv;
    o[lane + 32] = bias2[lane + 32] + acc1 * inv;
}

// ---------------- classifier ----------------
__global__ void k_cls(const float* __restrict__ Wc, const float* __restrict__ bc,
                      float* __restrict__ out) {
    int i = blockIdx.x * blockDim.x + threadIdx.x;
    if (i >= NN * 10) return;
    int n = i / 10, j = i % 10;
    const float* h = d_h2 + (size_t)n * 64;
    float acc = bc[j];
    #pragma unroll 16
    for (int k = 0; k < 64; k++) acc += h[k] * Wc[k * 10 + j];
    out[i] = acc;
}

// ---------------- launch ----------------
extern "C" void kernel_launch(void* const* d_in, const int* in_sizes, int n_in,
                              void* d_out, int out_size) {
    const float* x    = (const float*)d_in[0];
    const int*   ei   = (const int*)d_in[1];
    const float* c1w  = (const float*)d_in[2];
    const float* c1b  = (const float*)d_in[3];
    const float* c2w  = (const float*)d_in[4];
    const float* c2b  = (const float*)d_in[5];
    const float* Wl1  = (const float*)d_in[6];
    const float* bl1  = (const float*)d_in[7];
    const float* Wr1  = (const float*)d_in[8];
    const float* br1  = (const float*)d_in[9];
    const float* att1 = (const float*)d_in[10];
    const float* bias1= (const float*)d_in[11];
    const float* Wl2  = (const float*)d_in[12];
    const float* bl2  = (const float*)d_in[13];
    const float* Wr2  = (const float*)d_in[14];
    const float* br2  = (const float*)d_in[15];
    const float* att2 = (const float*)d_in[16];
    const float* bias2= (const float*)d_in[17];
    const float* Wc   = (const float*)d_in[18];
    const float* bc   = (const float*)d_in[19];
    float* out = (float*)d_out;

    int Eraw = in_sizes[1] / 2;
    int nodeBlocks = NN / 8;

    // Order keeps k_convf in ncu capture slot #4:
    // deg(1), hist(2), scan(3), convf(4), scatter(5), ...
    k_deg_init<<<NN / 256, 256>>>();
    k_hist<<<(Eraw + 255) / 256, 256>>>(ei, Eraw);
    k_scan<<<1, 1024>>>();
    k_convf<<<NN, 256>>>(x, c1w, c1b, c2w, c2b);
    k_scatter<<<(Eraw + 255) / 256, 256>>>(ei, Eraw);

    // GAT layer 1 (dual GEMM: xl1+xr1 in one pass over A)
    k_gemmd<0><<<dim3(2, NN / 128), 256>>>(Wl1, bl1, Wr1, br1, GIN, 128);
    k_gat1<<<nodeBlocks, 256>>>(att1, bias1);

    // GAT layer 2
    k_gemmd<1><<<dim3(1, NN / 128), 256>>>(Wl2, bl2, Wr2, br2, 128, 64);
    k_gat2<<<nodeBlocks, 256>>>(att2, bias2);

    // classifier
    k_cls<<<(NN * 10 + 255) / 256, 256>>>(Wc, bc, out);
}